// round 3
// baseline (speedup 1.0000x reference)
#include <cuda_runtime.h>
#include <math.h>

// Problem constants
#define BB 2
#define SS 2048
#define HH 1024
#define NH 16
#define HD 64
#define MM (BB*SS)          // 4096 rows
#define STRIDE 45
#define SUMC 1

// Scratch (device globals: allocation-free per harness rules)
__device__ float g_q[BB*NH*SS*HD];   // [B, nh, S, hd]
__device__ float g_k[BB*NH*SS*HD];
__device__ float g_v[BB*NH*SS*HD];
__device__ float g_o[BB*SS*HH];      // attention out, [B, S, H]

// ---------------------------------------------------------------------------
// Fused QKV projection: q/k/v[m, n] = sum_k x[m,k] * W{q,k,v}[n,k]
// Writes directly into head-split layout [B, nh, S, hd].
// 64x64 output tile per block, K-tile 32, 4x4 register blocking, 256 threads.
// ---------------------------------------------------------------------------
__global__ __launch_bounds__(256, 1)
void qkv_kernel(const float* __restrict__ x,
                const float* __restrict__ Wq,
                const float* __restrict__ Wk,
                const float* __restrict__ Wv)
{
    __shared__ float Xs[64][33];
    __shared__ float Aq[64][33];
    __shared__ float Ak[64][33];
    __shared__ float Av[64][33];

    const int n0 = blockIdx.x * 64;
    const int m0 = blockIdx.y * 64;
    const int tid = threadIdx.x;
    const int tx = tid & 15;
    const int ty = tid >> 4;

    float accq[16], acck[16], accv[16];
#pragma unroll
    for (int i = 0; i < 16; i++) { accq[i] = 0.f; acck[i] = 0.f; accv[i] = 0.f; }

    for (int k0 = 0; k0 < HH; k0 += 32) {
#pragma unroll
        for (int idx = tid; idx < 64*32; idx += 256) {
            int r = idx >> 5, c = idx & 31;
            Xs[r][c] = x [(m0 + r) * HH + k0 + c];
            Aq[r][c] = Wq[(n0 + r) * HH + k0 + c];
            Ak[r][c] = Wk[(n0 + r) * HH + k0 + c];
            Av[r][c] = Wv[(n0 + r) * HH + k0 + c];
        }
        __syncthreads();
#pragma unroll
        for (int kk = 0; kk < 32; kk++) {
            float a[4], bq[4], bk[4], bv[4];
#pragma unroll
            for (int r = 0; r < 4; r++) a[r] = Xs[ty*4 + r][kk];
#pragma unroll
            for (int c = 0; c < 4; c++) {
                bq[c] = Aq[tx*4 + c][kk];
                bk[c] = Ak[tx*4 + c][kk];
                bv[c] = Av[tx*4 + c][kk];
            }
#pragma unroll
            for (int r = 0; r < 4; r++)
#pragma unroll
                for (int c = 0; c < 4; c++) {
                    accq[r*4+c] = fmaf(a[r], bq[c], accq[r*4+c]);
                    acck[r*4+c] = fmaf(a[r], bk[c], acck[r*4+c]);
                    accv[r*4+c] = fmaf(a[r], bv[c], accv[r*4+c]);
                }
        }
        __syncthreads();
    }

#pragma unroll
    for (int r = 0; r < 4; r++) {
        int m = m0 + ty*4 + r;
        int b = m >> 11;          // / 2048
        int s = m & 2047;
#pragma unroll
        for (int c = 0; c < 4; c++) {
            int n = n0 + tx*4 + c;
            int h = n >> 6;       // / 64
            int d = n & 63;
            int o = ((b*NH + h)*SS + s)*HD + d;
            g_q[o] = accq[r*4+c];
            g_k[o] = acck[r*4+c];
            g_v[o] = accv[r*4+c];
        }
    }
}

// ---------------------------------------------------------------------------
// Masked flash attention: one block = 64-query tile for (b, head).
// Streams 64-key tiles with online softmax; mask evaluated per element.
// Dynamic smem: Qs/Ks/Vs/Ps each 64x65 floats = 66560 bytes.
// ---------------------------------------------------------------------------
#define ATTN_SMEM (4 * 64 * 65 * 4)

__global__ __launch_bounds__(256, 1)
void attn_kernel()
{
    extern __shared__ float smem[];
    float (*Qs)[65] = (float (*)[65])(smem);
    float (*Ks)[65] = (float (*)[65])(smem + 64*65);
    float (*Vs)[65] = (float (*)[65])(smem + 2*64*65);
    float (*Ps)[65] = (float (*)[65])(smem + 3*64*65);

    const int qt = blockIdx.x;
    const int h  = blockIdx.y;
    const int b  = blockIdx.z;
    const int i0 = qt * 64;
    const bool strided_head = (h < NH/2);

    const float* __restrict__ qb = g_q + (size_t)(b*NH + h) * SS * HD;
    const float* __restrict__ kb = g_k + (size_t)(b*NH + h) * SS * HD;
    const float* __restrict__ vb = g_v + (size_t)(b*NH + h) * SS * HD;

    const int tid = threadIdx.x;
    const int tx = tid & 15;
    const int ty = tid >> 4;

    // load Q tile
    for (int idx = tid; idx < 64*64; idx += 256) {
        int r = idx >> 6, d = idx & 63;
        Qs[r][d] = qb[(i0 + r) * HD + d];
    }

    float acc[16];
#pragma unroll
    for (int i = 0; i < 16; i++) acc[i] = 0.f;
    float mrow[4], lrow[4];
    int   irow[4], imod[4], idiv[4];
#pragma unroll
    for (int r = 0; r < 4; r++) {
        mrow[r] = -1e30f;
        lrow[r] = 0.f;
        irow[r] = i0 + ty*4 + r;
        imod[r] = irow[r] % STRIDE;
        idiv[r] = irow[r] / STRIDE;
    }

    for (int j0 = 0; j0 <= i0; j0 += 64) {
        __syncthreads();   // previous tile's smem reads done (also covers Q load)
        for (int idx = tid; idx < 64*64; idx += 256) {
            int r = idx >> 6, d = idx & 63;
            Ks[r][d] = kb[(j0 + r) * HD + d];
            Vs[r][d] = vb[(j0 + r) * HD + d];
        }
        __syncthreads();

        // scores = Q K^T
        float sc[16];
#pragma unroll
        for (int i = 0; i < 16; i++) sc[i] = 0.f;
#pragma unroll
        for (int kk = 0; kk < 64; kk++) {
            float a[4], bk2[4];
#pragma unroll
            for (int r = 0; r < 4; r++) a[r] = Qs[ty*4 + r][kk];
#pragma unroll
            for (int c = 0; c < 4; c++) bk2[c] = Ks[tx*4 + c][kk];
#pragma unroll
            for (int r = 0; r < 4; r++)
#pragma unroll
                for (int c = 0; c < 4; c++)
                    sc[r*4+c] = fmaf(a[r], bk2[c], sc[r*4+c]);
        }

        // scale + mask
#pragma unroll
        for (int r = 0; r < 4; r++) {
            int i = irow[r];
#pragma unroll
            for (int c = 0; c < 4; c++) {
                int j = j0 + tx*4 + c;
                int jmod = j % STRIDE;
                bool ok;
                if (strided_head) {
                    ok = (j <= i) && ((i - j < STRIDE) || (jmod == imod[r]));
                } else {
                    ok = (j <= i) && ((j / STRIDE == idiv[r]) || (jmod >= STRIDE - SUMC));
                }
                sc[r*4+c] = ok ? sc[r*4+c] * 0.125f : -1e30f;
            }
        }

        // online softmax (row = 16 contiguous lanes)
#pragma unroll
        for (int r = 0; r < 4; r++) {
            float tmax = fmaxf(fmaxf(sc[r*4+0], sc[r*4+1]),
                               fmaxf(sc[r*4+2], sc[r*4+3]));
#pragma unroll
            for (int off = 8; off; off >>= 1)
                tmax = fmaxf(tmax, __shfl_xor_sync(0xffffffffu, tmax, off));
            float newm = fmaxf(mrow[r], tmax);
            float alpha = __expf(mrow[r] - newm);
            float ps = 0.f;
#pragma unroll
            for (int c = 0; c < 4; c++) {
                float p = __expf(sc[r*4+c] - newm);
                sc[r*4+c] = p;
                ps += p;
            }
#pragma unroll
            for (int off = 8; off; off >>= 1)
                ps += __shfl_xor_sync(0xffffffffu, ps, off);
            mrow[r] = newm;
            lrow[r] = lrow[r] * alpha + ps;
#pragma unroll
            for (int c = 0; c < 4; c++) acc[r*4+c] *= alpha;
        }

        // write P tile and do P·V
#pragma unroll
        for (int r = 0; r < 4; r++)
#pragma unroll
            for (int c = 0; c < 4; c++)
                Ps[ty*4 + r][tx*4 + c] = sc[r*4+c];
        __syncthreads();

#pragma unroll
        for (int kk = 0; kk < 64; kk++) {
            float p[4], vv[4];
#pragma unroll
            for (int r = 0; r < 4; r++) p[r] = Ps[ty*4 + r][kk];
#pragma unroll
            for (int c = 0; c < 4; c++) vv[c] = Vs[kk][tx*4 + c];
#pragma unroll
            for (int r = 0; r < 4; r++)
#pragma unroll
                for (int c = 0; c < 4; c++)
                    acc[r*4+c] = fmaf(p[r], vv[c], acc[r*4+c]);
        }
    }

    // epilogue -> g_o [B, S, H]
#pragma unroll
    for (int r = 0; r < 4; r++) {
        float inv = 1.f / lrow[r];
        int i = irow[r];
#pragma unroll
        for (int c = 0; c < 4; c++) {
            int n = h * HD + tx*4 + c;
            g_o[((size_t)b * SS + i) * HH + n] = acc[r*4+c] * inv;
        }
    }
}

// ---------------------------------------------------------------------------
// Output projection: out[m,n] = sum_k g_o[m,k] * Wo[n,k]
// ---------------------------------------------------------------------------
__global__ __launch_bounds__(256, 1)
void out_proj_kernel(const float* __restrict__ Wo, float* __restrict__ out)
{
    __shared__ float Xs[64][33];
    __shared__ float Ws[64][33];

    const int n0 = blockIdx.x * 64;
    const int m0 = blockIdx.y * 64;
    const int tid = threadIdx.x;
    const int tx = tid & 15;
    const int ty = tid >> 4;

    float acc[16];
#pragma unroll
    for (int i = 0; i < 16; i++) acc[i] = 0.f;

    for (int k0 = 0; k0 < HH; k0 += 32) {
#pragma unroll
        for (int idx = tid; idx < 64*32; idx += 256) {
            int r = idx >> 5, c = idx & 31;
            Xs[r][c] = g_o[(size_t)(m0 + r) * HH + k0 + c];
            Ws[r][c] = Wo [(n0 + r) * HH + k0 + c];
        }
        __syncthreads();
#pragma unroll
        for (int kk = 0; kk < 32; kk++) {
            float a[4], bw[4];
#pragma unroll
            for (int r = 0; r < 4; r++) a[r] = Xs[ty*4 + r][kk];
#pragma unroll
            for (int c = 0; c < 4; c++) bw[c] = Ws[tx*4 + c][kk];
#pragma unroll
            for (int r = 0; r < 4; r++)
#pragma unroll
                for (int c = 0; c < 4; c++)
                    acc[r*4+c] = fmaf(a[r], bw[c], acc[r*4+c]);
        }
        __syncthreads();
    }

#pragma unroll
    for (int r = 0; r < 4; r++) {
        int m = m0 + ty*4 + r;
#pragma unroll
        for (int c = 0; c < 4; c++) {
            int n = n0 + tx*4 + c;
            out[(size_t)m * HH + n] = acc[r*4+c];
        }
    }
}

// ---------------------------------------------------------------------------
extern "C" void kernel_launch(void* const* d_in, const int* in_sizes, int n_in,
                              void* d_out, int out_size)
{
    const float* x  = (const float*)d_in[0];
    const float* Wq = (const float*)d_in[1];
    const float* Wk = (const float*)d_in[2];
    const float* Wv = (const float*)d_in[3];
    const float* Wo = (const float*)d_in[4];
    float* out = (float*)d_out;

    cudaFuncSetAttribute(attn_kernel,
                         cudaFuncAttributeMaxDynamicSharedMemorySize, ATTN_SMEM);

    qkv_kernel<<<dim3(HH/64, MM/64), 256>>>(x, Wq, Wk, Wv);
    attn_kernel<<<dim3(SS/64, NH, BB), 256, ATTN_SMEM>>>();
    out_proj_kernel<<<dim3(HH/64, MM/64), 256>>>(Wo, out);
}

// round 4
// speedup vs baseline: 2.6283x; 2.6283x over previous
#include <cuda_runtime.h>
#include <math.h>

// Problem constants
#define BB 2
#define SS 2048
#define HH 1024
#define NH 16
#define HD 64
#define MM (BB*SS)
#define STRIDE 45
#define SUMC 1

// Scratch (device globals: allocation-free per harness rules)
__device__ float g_q[BB*NH*SS*HD];   // [B, nh, S, hd]
__device__ float g_k[BB*NH*SS*HD];
__device__ float g_v[BB*NH*SS*HD];
__device__ float g_o[BB*SS*HH];      // attention out, [B, S, H]

// ---------------------------------------------------------------------------
// helpers
// ---------------------------------------------------------------------------
__device__ __forceinline__ unsigned f2tf(float x) {
    unsigned u; asm("cvt.rna.tf32.f32 %0, %1;" : "=r"(u) : "f"(x)); return u;
}
__device__ __forceinline__ void mma8(float c[4], const unsigned a[4], const unsigned b[2]) {
    asm volatile("mma.sync.aligned.m16n8k8.row.col.f32.tf32.tf32.f32 "
        "{%0,%1,%2,%3}, {%4,%5,%6,%7}, {%8,%9}, {%0,%1,%2,%3};"
        : "+f"(c[0]), "+f"(c[1]), "+f"(c[2]), "+f"(c[3])
        : "r"(a[0]), "r"(a[1]), "r"(a[2]), "r"(a[3]), "r"(b[0]), "r"(b[1]));
}
__device__ __forceinline__ void cpa16(float* s, const float* g) {
    unsigned sa = (unsigned)__cvta_generic_to_shared(s);
    asm volatile("cp.async.cg.shared.global [%0], [%1], 16;" :: "r"(sa), "l"(g));
}

// ---------------------------------------------------------------------------
// QKV projection, tf32 mma. 128x128 block tile, K-tile 32, double buffered.
// grid.x: 3 mats * 8 n-blocks; grid.y: 32 m-blocks. 256 threads.
// ---------------------------------------------------------------------------
#define RP 36                 // smem row pitch (floats)
#define GEMM_SMEM (4*128*RP*4)  // 73728 B

__global__ __launch_bounds__(256, 2)
void qkv_mma(const float* __restrict__ x,  const float* __restrict__ Wq,
             const float* __restrict__ Wk, const float* __restrict__ Wv)
{
    extern __shared__ float sm[];
    float* Abuf[2] = { sm,            sm + 128*RP   };
    float* Bbuf[2] = { sm + 2*128*RP, sm + 3*128*RP };

    const int sel = blockIdx.x >> 3;
    const float* __restrict__ W = (sel == 0) ? Wq : (sel == 1) ? Wk : Wv;
    const int n0 = (blockIdx.x & 7) * 128;
    const int m0 = blockIdx.y * 128;

    const int tid  = threadIdx.x;
    const int warp = tid >> 5;
    const int lane = tid & 31;
    const int g = lane >> 2;
    const int t = lane & 3;
    const int wm = warp >> 2;     // 0..1 -> 64-row half
    const int wn = warp & 3;      // 0..3 -> 32-col quarter

    float c[4][4][4];
#pragma unroll
    for (int i = 0; i < 4; i++)
#pragma unroll
        for (int j = 0; j < 4; j++)
#pragma unroll
            for (int k = 0; k < 4; k++) c[i][j][k] = 0.f;

    // prefetch tile 0
#pragma unroll
    for (int i = 0; i < 4; i++) {
        int f = tid + i*256;                // 1024 float4 per matrix
        int r = f >> 3, c4 = (f & 7) * 4;
        cpa16(Abuf[0] + r*RP + c4, x + (size_t)(m0+r)*HH + c4);
        cpa16(Bbuf[0] + r*RP + c4, W + (size_t)(n0+r)*HH + c4);
    }
    asm volatile("cp.async.commit_group;");

    const int NT = HH / 32;
    for (int ti = 0; ti < NT; ti++) {
        asm volatile("cp.async.wait_group 0;");
        __syncthreads();
        const int cur = ti & 1;
        if (ti + 1 < NT) {
            const int k0 = (ti+1) * 32;
            const int nxt = cur ^ 1;
#pragma unroll
            for (int i = 0; i < 4; i++) {
                int f = tid + i*256;
                int r = f >> 3, c4 = (f & 7) * 4;
                cpa16(Abuf[nxt] + r*RP + c4, x + (size_t)(m0+r)*HH + k0 + c4);
                cpa16(Bbuf[nxt] + r*RP + c4, W + (size_t)(n0+r)*HH + k0 + c4);
            }
            asm volatile("cp.async.commit_group;");
        }
        const float* As = Abuf[cur];
        const float* Bs = Bbuf[cur];
#pragma unroll
        for (int ks = 0; ks < 4; ks++) {
            const int col = ks*8 + t;
            unsigned a[4][4], b[4][2];
#pragma unroll
            for (int mf = 0; mf < 4; mf++) {
                int r = wm*64 + mf*16 + g;
                a[mf][0] = f2tf(As[r*RP + col]);
                a[mf][1] = f2tf(As[(r+8)*RP + col]);
                a[mf][2] = f2tf(As[r*RP + col + 4]);
                a[mf][3] = f2tf(As[(r+8)*RP + col + 4]);
            }
#pragma unroll
            for (int nf = 0; nf < 4; nf++) {
                int n = wn*32 + nf*8 + g;
                b[nf][0] = f2tf(Bs[n*RP + col]);
                b[nf][1] = f2tf(Bs[n*RP + col + 4]);
            }
#pragma unroll
            for (int mf = 0; mf < 4; mf++)
#pragma unroll
                for (int nf = 0; nf < 4; nf++)
                    mma8(c[mf][nf], a[mf], b[nf]);
        }
        __syncthreads();
    }

    float* dst = (sel == 0) ? g_q : (sel == 1) ? g_k : g_v;
#pragma unroll
    for (int mf = 0; mf < 4; mf++) {
#pragma unroll
        for (int half = 0; half < 2; half++) {
            int m = m0 + wm*64 + mf*16 + g + half*8;
            int bb = m >> 11, s = m & 2047;
#pragma unroll
            for (int nf = 0; nf < 4; nf++) {
                int n = n0 + wn*32 + nf*8 + 2*t;
                int h = n >> 6, d = n & 63;
                float2 v2 = half ? make_float2(c[mf][nf][2], c[mf][nf][3])
                                 : make_float2(c[mf][nf][0], c[mf][nf][1]);
                *(float2*)&dst[(((size_t)(bb*NH + h))*SS + s)*HD + d] = v2;
            }
        }
    }
}

// ---------------------------------------------------------------------------
// Masked flash attention, tf32 mma. 64-query tile per block, 4 warps.
// ---------------------------------------------------------------------------
#define APAD 68
#define ATTN_SMEM ((4*64*APAD + 128) * 4)   // 70144 B

__global__ __launch_bounds__(128)
void attn_mma()
{
    extern __shared__ float sm[];
    float* Qs = sm;
    float* Ks = sm + 64*APAD;
    float* Vs = sm + 2*64*APAD;
    float* Ps = sm + 3*64*APAD;
    int* jm = (int*)(sm + 4*64*APAD);
    int* jd = jm + 64;

    const int qt = blockIdx.x, h = blockIdx.y, b = blockIdx.z;
    const int i0 = qt * 64;
    const bool strided_head = (h < NH/2);

    const float* __restrict__ qb = g_q + (size_t)(b*NH + h) * SS * HD;
    const float* __restrict__ kb = g_k + (size_t)(b*NH + h) * SS * HD;
    const float* __restrict__ vb = g_v + (size_t)(b*NH + h) * SS * HD;

    const int tid = threadIdx.x;
    const int warp = tid >> 5, lane = tid & 31;
    const int g = lane >> 2, t = lane & 3;

    // load Q tile
#pragma unroll
    for (int i = 0; i < 8; i++) {
        int f = tid + i*128;                 // 1024 float4
        int r = f >> 4, c4 = (f & 15) * 4;
        *(float4*)(Qs + r*APAD + c4) = *(const float4*)(qb + (size_t)(i0+r)*HD + c4);
    }

    const int r0 = i0 + warp*16 + g;
    const int r1 = r0 + 8;
    const int im0 = r0 % STRIDE, id0 = r0 / STRIDE;
    const int im1 = r1 % STRIDE, id1 = r1 / STRIDE;

    float o[8][4];
#pragma unroll
    for (int i = 0; i < 8; i++)
#pragma unroll
        for (int k = 0; k < 4; k++) o[i][k] = 0.f;
    float m0r = -1e30f, m1r = -1e30f, l0 = 0.f, l1 = 0.f;

    const int NT = i0/64 + 1;
    for (int ti = 0; ti < NT; ti++) {
        const int j0 = ti * 64;
        __syncthreads();                 // prior K/V reads done (covers Q store too)
#pragma unroll
        for (int i = 0; i < 8; i++) {
            int f = tid + i*128;
            int r = f >> 4, c4 = (f & 15) * 4;
            *(float4*)(Ks + r*APAD + c4) = *(const float4*)(kb + (size_t)(j0+r)*HD + c4);
            *(float4*)(Vs + r*APAD + c4) = *(const float4*)(vb + (size_t)(j0+r)*HD + c4);
        }
        if (tid < 64) { int j = j0 + tid; jm[tid] = j % STRIDE; jd[tid] = j / STRIDE; }
        __syncthreads();

        // scores = Q K^T (16 rows per warp x 64 cols)
        float sc[8][4];
#pragma unroll
        for (int i = 0; i < 8; i++)
#pragma unroll
            for (int k = 0; k < 4; k++) sc[i][k] = 0.f;
        const int qr = warp*16 + g;
#pragma unroll
        for (int ks = 0; ks < 8; ks++) {
            const int col = ks*8 + t;
            unsigned a[4];
            a[0] = f2tf(Qs[qr*APAD + col]);
            a[1] = f2tf(Qs[(qr+8)*APAD + col]);
            a[2] = f2tf(Qs[qr*APAD + col + 4]);
            a[3] = f2tf(Qs[(qr+8)*APAD + col + 4]);
#pragma unroll
            for (int nf = 0; nf < 8; nf++) {
                unsigned bf[2];
                bf[0] = f2tf(Ks[(nf*8+g)*APAD + col]);
                bf[1] = f2tf(Ks[(nf*8+g)*APAD + col + 4]);
                mma8(sc[nf], a, bf);
            }
        }

        // mask + scale
#pragma unroll
        for (int nf = 0; nf < 8; nf++) {
#pragma unroll
            for (int ci = 0; ci < 2; ci++) {
                int jj = nf*8 + 2*t + ci;
                int j = j0 + jj;
                int jmv = jm[jj], jdv = jd[jj];
                bool ok0, ok1;
                if (strided_head) {
                    ok0 = (j <= r0) && ((r0 - j < STRIDE) || (jmv == im0));
                    ok1 = (j <= r1) && ((r1 - j < STRIDE) || (jmv == im1));
                } else {
                    ok0 = (j <= r0) && ((jdv == id0) || (jmv >= STRIDE - SUMC));
                    ok1 = (j <= r1) && ((jdv == id1) || (jmv >= STRIDE - SUMC));
                }
                sc[nf][ci]     = ok0 ? sc[nf][ci]     * 0.125f : -1e30f;
                sc[nf][2 + ci] = ok1 ? sc[nf][2 + ci] * 0.125f : -1e30f;
            }
        }

        // online softmax: rows r0 (c0,c1) and r1 (c2,c3); 4 lanes share a row
        float mx0 = -1e30f, mx1 = -1e30f;
#pragma unroll
        for (int nf = 0; nf < 8; nf++) {
            mx0 = fmaxf(mx0, fmaxf(sc[nf][0], sc[nf][1]));
            mx1 = fmaxf(mx1, fmaxf(sc[nf][2], sc[nf][3]));
        }
        mx0 = fmaxf(mx0, __shfl_xor_sync(0xffffffffu, mx0, 1));
        mx0 = fmaxf(mx0, __shfl_xor_sync(0xffffffffu, mx0, 2));
        mx1 = fmaxf(mx1, __shfl_xor_sync(0xffffffffu, mx1, 1));
        mx1 = fmaxf(mx1, __shfl_xor_sync(0xffffffffu, mx1, 2));
        float nm0 = fmaxf(m0r, mx0), nm1 = fmaxf(m1r, mx1);
        float al0 = __expf(m0r - nm0), al1 = __expf(m1r - nm1);
        float ps0 = 0.f, ps1 = 0.f;
#pragma unroll
        for (int nf = 0; nf < 8; nf++) {
            float p0 = __expf(sc[nf][0] - nm0); sc[nf][0] = p0; ps0 += p0;
            float p1 = __expf(sc[nf][1] - nm0); sc[nf][1] = p1; ps0 += p1;
            float p2 = __expf(sc[nf][2] - nm1); sc[nf][2] = p2; ps1 += p2;
            float p3 = __expf(sc[nf][3] - nm1); sc[nf][3] = p3; ps1 += p3;
        }
        ps0 += __shfl_xor_sync(0xffffffffu, ps0, 1);
        ps0 += __shfl_xor_sync(0xffffffffu, ps0, 2);
        ps1 += __shfl_xor_sync(0xffffffffu, ps1, 1);
        ps1 += __shfl_xor_sync(0xffffffffu, ps1, 2);
        m0r = nm0; m1r = nm1;
        l0 = l0*al0 + ps0;
        l1 = l1*al1 + ps1;
#pragma unroll
        for (int nf = 0; nf < 8; nf++) {
            o[nf][0] *= al0; o[nf][1] *= al0;
            o[nf][2] *= al1; o[nf][3] *= al1;
        }

        // stage P in smem (rows are warp-private; only warp-level sync needed)
#pragma unroll
        for (int nf = 0; nf < 8; nf++) {
            Ps[qr*APAD     + nf*8 + 2*t]     = sc[nf][0];
            Ps[qr*APAD     + nf*8 + 2*t + 1] = sc[nf][1];
            Ps[(qr+8)*APAD + nf*8 + 2*t]     = sc[nf][2];
            Ps[(qr+8)*APAD + nf*8 + 2*t + 1] = sc[nf][3];
        }
        __syncwarp();

        // O += P @ V
#pragma unroll
        for (int ks = 0; ks < 8; ks++) {
            const int col = ks*8 + t;
            unsigned a[4];
            a[0] = f2tf(Ps[qr*APAD + col]);
            a[1] = f2tf(Ps[(qr+8)*APAD + col]);
            a[2] = f2tf(Ps[qr*APAD + col + 4]);
            a[3] = f2tf(Ps[(qr+8)*APAD + col + 4]);
#pragma unroll
            for (int nf = 0; nf < 8; nf++) {
                unsigned bf[2];
                bf[0] = f2tf(Vs[col*APAD     + nf*8 + g]);
                bf[1] = f2tf(Vs[(col+4)*APAD + nf*8 + g]);
                mma8(o[nf], a, bf);
            }
        }
        __syncwarp();
    }

    // epilogue -> g_o [B, S, H]
    const float inv0 = 1.f / l0, inv1 = 1.f / l1;
#pragma unroll
    for (int nf = 0; nf < 8; nf++) {
        int d = h*HD + nf*8 + 2*t;
        *(float2*)&g_o[((size_t)b*SS + r0)*HH + d] =
            make_float2(o[nf][0]*inv0, o[nf][1]*inv0);
        *(float2*)&g_o[((size_t)b*SS + r1)*HH + d] =
            make_float2(o[nf][2]*inv1, o[nf][3]*inv1);
    }
}

// ---------------------------------------------------------------------------
// Output projection, tf32 mma. Same skeleton as qkv_mma.
// ---------------------------------------------------------------------------
__global__ __launch_bounds__(256, 2)
void oproj_mma(const float* __restrict__ Wo, float* __restrict__ out)
{
    extern __shared__ float sm[];
    float* Abuf[2] = { sm,            sm + 128*RP   };
    float* Bbuf[2] = { sm + 2*128*RP, sm + 3*128*RP };

    const int n0 = blockIdx.x * 128;
    const int m0 = blockIdx.y * 128;

    const int tid  = threadIdx.x;
    const int warp = tid >> 5;
    const int lane = tid & 31;
    const int g = lane >> 2;
    const int t = lane & 3;
    const int wm = warp >> 2;
    const int wn = warp & 3;

    float c[4][4][4];
#pragma unroll
    for (int i = 0; i < 4; i++)
#pragma unroll
        for (int j = 0; j < 4; j++)
#pragma unroll
            for (int k = 0; k < 4; k++) c[i][j][k] = 0.f;

#pragma unroll
    for (int i = 0; i < 4; i++) {
        int f = tid + i*256;
        int r = f >> 3, c4 = (f & 7) * 4;
        cpa16(Abuf[0] + r*RP + c4, g_o + (size_t)(m0+r)*HH + c4);
        cpa16(Bbuf[0] + r*RP + c4, Wo  + (size_t)(n0+r)*HH + c4);
    }
    asm volatile("cp.async.commit_group;");

    const int NT = HH / 32;
    for (int ti = 0; ti < NT; ti++) {
        asm volatile("cp.async.wait_group 0;");
        __syncthreads();
        const int cur = ti & 1;
        if (ti + 1 < NT) {
            const int k0 = (ti+1) * 32;
            const int nxt = cur ^ 1;
#pragma unroll
            for (int i = 0; i < 4; i++) {
                int f = tid + i*256;
                int r = f >> 3, c4 = (f & 7) * 4;
                cpa16(Abuf[nxt] + r*RP + c4, g_o + (size_t)(m0+r)*HH + k0 + c4);
                cpa16(Bbuf[nxt] + r*RP + c4, Wo  + (size_t)(n0+r)*HH + k0 + c4);
            }
            asm volatile("cp.async.commit_group;");
        }
        const float* As = Abuf[cur];
        const float* Bs = Bbuf[cur];
#pragma unroll
        for (int ks = 0; ks < 4; ks++) {
            const int col = ks*8 + t;
            unsigned a[4][4], b[4][2];
#pragma unroll
            for (int mf = 0; mf < 4; mf++) {
                int r = wm*64 + mf*16 + g;
                a[mf][0] = f2tf(As[r*RP + col]);
                a[mf][1] = f2tf(As[(r+8)*RP + col]);
                a[mf][2] = f2tf(As[r*RP + col + 4]);
                a[mf][3] = f2tf(As[(r+8)*RP + col + 4]);
            }
#pragma unroll
            for (int nf = 0; nf < 4; nf++) {
                int n = wn*32 + nf*8 + g;
                b[nf][0] = f2tf(Bs[n*RP + col]);
                b[nf][1] = f2tf(Bs[n*RP + col + 4]);
            }
#pragma unroll
            for (int mf = 0; mf < 4; mf++)
#pragma unroll
                for (int nf = 0; nf < 4; nf++)
                    mma8(c[mf][nf], a[mf], b[nf]);
        }
        __syncthreads();
    }

#pragma unroll
    for (int mf = 0; mf < 4; mf++) {
#pragma unroll
        for (int half = 0; half < 2; half++) {
            int m = m0 + wm*64 + mf*16 + g + half*8;
#pragma unroll
            for (int nf = 0; nf < 4; nf++) {
                int n = n0 + wn*32 + nf*8 + 2*t;
                float2 v2 = half ? make_float2(c[mf][nf][2], c[mf][nf][3])
                                 : make_float2(c[mf][nf][0], c[mf][nf][1]);
                *(float2*)&out[(size_t)m*HH + n] = v2;
            }
        }
    }
}

// ---------------------------------------------------------------------------
extern "C" void kernel_launch(void* const* d_in, const int* in_sizes, int n_in,
                              void* d_out, int out_size)
{
    const float* x  = (const float*)d_in[0];
    const float* Wq = (const float*)d_in[1];
    const float* Wk = (const float*)d_in[2];
    const float* Wv = (const float*)d_in[3];
    const float* Wo = (const float*)d_in[4];
    float* out = (float*)d_out;

    cudaFuncSetAttribute(qkv_mma,   cudaFuncAttributeMaxDynamicSharedMemorySize, GEMM_SMEM);
    cudaFuncSetAttribute(attn_mma,  cudaFuncAttributeMaxDynamicSharedMemorySize, ATTN_SMEM);
    cudaFuncSetAttribute(oproj_mma, cudaFuncAttributeMaxDynamicSharedMemorySize, GEMM_SMEM);

    qkv_mma<<<dim3(24, 32), 256, GEMM_SMEM>>>(x, Wq, Wk, Wv);
    attn_mma<<<dim3(SS/64, NH, BB), 128, ATTN_SMEM>>>();
    oproj_mma<<<dim3(8, 32), 256, GEMM_SMEM>>>(Wo, out);
}

// round 6
// speedup vs baseline: 3.4101x; 1.2974x over previous
#include <cuda_runtime.h>
#include <math.h>

// Problem constants
#define BB 2
#define SS 2048
#define HH 1024
#define NH 16
#define HD 64
#define MM (BB*SS)
#define STRIDE 45
#define SUMC 1

// Scratch (device globals: allocation-free per harness rules)
__device__ float g_q[BB*NH*SS*HD];   // [B, nh, S, hd]  (tf32-rounded)
__device__ float g_k[BB*NH*SS*HD];
__device__ float g_v[BB*NH*SS*HD];
__device__ float g_o[BB*SS*HH];      // attention out, [B, S, H] (tf32-rounded)
__device__ float g_xt[MM*HH];        // tf32-rounded inputs/weights
__device__ float g_wt[3*HH*HH];      // Wq, Wk, Wv
__device__ float g_wot[HH*HH];

// ---------------------------------------------------------------------------
// helpers
// ---------------------------------------------------------------------------
__device__ __forceinline__ unsigned f2tf(float x) {
    unsigned u; asm("cvt.rna.tf32.f32 %0, %1;" : "=r"(u) : "f"(x)); return u;
}
__device__ __forceinline__ float rtf(float x) { return __uint_as_float(f2tf(x)); }
__device__ __forceinline__ void mma8(float c[4], const unsigned a[4], const unsigned b[2]) {
    asm volatile("mma.sync.aligned.m16n8k8.row.col.f32.tf32.tf32.f32 "
        "{%0,%1,%2,%3}, {%4,%5,%6,%7}, {%8,%9}, {%0,%1,%2,%3};"
        : "+f"(c[0]), "+f"(c[1]), "+f"(c[2]), "+f"(c[3])
        : "r"(a[0]), "r"(a[1]), "r"(a[2]), "r"(a[3]), "r"(b[0]), "r"(b[1]));
}
__device__ __forceinline__ void cpa16(float* s, const float* g) {
    unsigned sa = (unsigned)__cvta_generic_to_shared(s);
    asm volatile("cp.async.cg.shared.global [%0], [%1], 16;" :: "r"(sa), "l"(g));
}

// ---------------------------------------------------------------------------
// Prologue: round x / Wq / Wk / Wv / Wo to tf32 (stored as f32 bits).
// ---------------------------------------------------------------------------
#define XF4 (MM*HH/4)      // 1048576
#define WF4 (HH*HH/4)      // 262144

__global__ __launch_bounds__(256)
void precvt(const float* __restrict__ x,  const float* __restrict__ Wq,
            const float* __restrict__ Wk, const float* __restrict__ Wv,
            const float* __restrict__ Wo)
{
    int i = blockIdx.x * 256 + threadIdx.x;
    const float4* s; float4* d; int k;
    if (i < XF4) { s = (const float4*)x; d = (float4*)g_xt; k = i; }
    else {
        int w = (i - XF4) >> 18;           // / WF4
        k = (i - XF4) & (WF4 - 1);
        const float* srcs[4] = { Wq, Wk, Wv, Wo };
        s = (const float4*)srcs[w];
        d = (w < 3) ? (float4*)(g_wt + (size_t)w*HH*HH) : (float4*)g_wot;
    }
    float4 v = s[k];
    v.x = rtf(v.x); v.y = rtf(v.y); v.z = rtf(v.z); v.w = rtf(v.w);
    d[k] = v;
}

// ---------------------------------------------------------------------------
// QKV projection, tf32 mma, pre-rounded operands (no in-loop cvt).
// 128x128 block tile, K-tile 32, double buffered. 256 threads.
// ---------------------------------------------------------------------------
#define RP 36
#define GEMM_SMEM (4*128*RP*4)  // 73728 B

__global__ __launch_bounds__(256, 2)
void qkv_mma()
{
    extern __shared__ float sm[];
    float* Abuf[2] = { sm,            sm + 128*RP   };
    float* Bbuf[2] = { sm + 2*128*RP, sm + 3*128*RP };

    const int sel = blockIdx.x >> 3;
    const float* __restrict__ W = g_wt + (size_t)sel*HH*HH;
    const float* __restrict__ x = g_xt;
    const int n0 = (blockIdx.x & 7) * 128;
    const int m0 = blockIdx.y * 128;

    const int tid  = threadIdx.x;
    const int warp = tid >> 5;
    const int lane = tid & 31;
    const int g = lane >> 2;
    const int t = lane & 3;
    const int wm = warp >> 2;
    const int wn = warp & 3;

    float c[4][4][4];
#pragma unroll
    for (int i = 0; i < 4; i++)
#pragma unroll
        for (int j = 0; j < 4; j++)
#pragma unroll
            for (int k = 0; k < 4; k++) c[i][j][k] = 0.f;

#pragma unroll
    for (int i = 0; i < 4; i++) {
        int f = tid + i*256;
        int r = f >> 3, c4 = (f & 7) * 4;
        cpa16(Abuf[0] + r*RP + c4, x + (size_t)(m0+r)*HH + c4);
        cpa16(Bbuf[0] + r*RP + c4, W + (size_t)(n0+r)*HH + c4);
    }
    asm volatile("cp.async.commit_group;");

    const int NT = HH / 32;
    for (int ti = 0; ti < NT; ti++) {
        asm volatile("cp.async.wait_group 0;");
        __syncthreads();
        const int cur = ti & 1;
        if (ti + 1 < NT) {
            const int k0 = (ti+1) * 32;
            const int nxt = cur ^ 1;
#pragma unroll
            for (int i = 0; i < 4; i++) {
                int f = tid + i*256;
                int r = f >> 3, c4 = (f & 7) * 4;
                cpa16(Abuf[nxt] + r*RP + c4, x + (size_t)(m0+r)*HH + k0 + c4);
                cpa16(Bbuf[nxt] + r*RP + c4, W + (size_t)(n0+r)*HH + k0 + c4);
            }
            asm volatile("cp.async.commit_group;");
        }
        const float* As = Abuf[cur];
        const float* Bs = Bbuf[cur];
#pragma unroll
        for (int ks = 0; ks < 4; ks++) {
            const int col = ks*8 + t;
            unsigned a[4][4], b[4][2];
#pragma unroll
            for (int mf = 0; mf < 4; mf++) {
                int r = wm*64 + mf*16 + g;
                a[mf][0] = __float_as_uint(As[r*RP + col]);
                a[mf][1] = __float_as_uint(As[(r+8)*RP + col]);
                a[mf][2] = __float_as_uint(As[r*RP + col + 4]);
                a[mf][3] = __float_as_uint(As[(r+8)*RP + col + 4]);
            }
#pragma unroll
            for (int nf = 0; nf < 4; nf++) {
                int n = wn*32 + nf*8 + g;
                b[nf][0] = __float_as_uint(Bs[n*RP + col]);
                b[nf][1] = __float_as_uint(Bs[n*RP + col + 4]);
            }
#pragma unroll
            for (int mf = 0; mf < 4; mf++)
#pragma unroll
                for (int nf = 0; nf < 4; nf++)
                    mma8(c[mf][nf], a[mf], b[nf]);
        }
        __syncthreads();
    }

    float* dst = (sel == 0) ? g_q : (sel == 1) ? g_k : g_v;
#pragma unroll
    for (int mf = 0; mf < 4; mf++) {
#pragma unroll
        for (int half = 0; half < 2; half++) {
            int m = m0 + wm*64 + mf*16 + g + half*8;
            int bb = m >> 11, s = m & 2047;
#pragma unroll
            for (int nf = 0; nf < 4; nf++) {
                int n = n0 + wn*32 + nf*8 + 2*t;
                int h = n >> 6, d = n & 63;
                float2 v2 = half ? make_float2(c[mf][nf][2], c[mf][nf][3])
                                 : make_float2(c[mf][nf][0], c[mf][nf][1]);
                v2.x = rtf(v2.x); v2.y = rtf(v2.y);   // pre-round for attention
                *(float2*)&dst[(((size_t)(bb*NH + h))*SS + s)*HD + d] = v2;
            }
        }
    }
}

// ---------------------------------------------------------------------------
// Strided-head flash attention (heads 0..7), dense causal tiles.
// ---------------------------------------------------------------------------
#define APAD 68
#define ATTN_SMEM ((4*64*APAD + 128) * 4)   // 70144 B

__global__ __launch_bounds__(128)
void attn_strided()
{
    extern __shared__ float sm[];
    float* Qs = sm;
    float* Ks = sm + 64*APAD;
    float* Vs = sm + 2*64*APAD;
    float* Ps = sm + 3*64*APAD;
    int* jm = (int*)(sm + 4*64*APAD);

    const int qt = blockIdx.x, h = blockIdx.y, b = blockIdx.z;
    const int i0 = qt * 64;

    const float* __restrict__ qb = g_q + (size_t)(b*NH + h) * SS * HD;
    const float* __restrict__ kb = g_k + (size_t)(b*NH + h) * SS * HD;
    const float* __restrict__ vb = g_v + (size_t)(b*NH + h) * SS * HD;

    const int tid = threadIdx.x;
    const int warp = tid >> 5, lane = tid & 31;
    const int g = lane >> 2, t = lane & 3;

#pragma unroll
    for (int i = 0; i < 8; i++) {
        int f = tid + i*128;
        int r = f >> 4, c4 = (f & 15) * 4;
        *(float4*)(Qs + r*APAD + c4) = *(const float4*)(qb + (size_t)(i0+r)*HD + c4);
    }

    const int r0 = i0 + warp*16 + g;
    const int r1 = r0 + 8;
    const int im0 = r0 % STRIDE, im1 = r1 % STRIDE;

    float o[8][4];
#pragma unroll
    for (int i = 0; i < 8; i++)
#pragma unroll
        for (int k = 0; k < 4; k++) o[i][k] = 0.f;
    float m0r = -1e30f, m1r = -1e30f, l0 = 0.f, l1 = 0.f;

    const int NT = i0/64 + 1;
    for (int ti = 0; ti < NT; ti++) {
        const int j0 = ti * 64;
        __syncthreads();
#pragma unroll
        for (int i = 0; i < 8; i++) {
            int f = tid + i*128;
            int r = f >> 4, c4 = (f & 15) * 4;
            *(float4*)(Ks + r*APAD + c4) = *(const float4*)(kb + (size_t)(j0+r)*HD + c4);
            *(float4*)(Vs + r*APAD + c4) = *(const float4*)(vb + (size_t)(j0+r)*HD + c4);
        }
        if (tid < 64) jm[tid] = (j0 + tid) % STRIDE;
        __syncthreads();

        float sc[8][4];
#pragma unroll
        for (int i = 0; i < 8; i++)
#pragma unroll
            for (int k = 0; k < 4; k++) sc[i][k] = 0.f;
        const int qr = warp*16 + g;
#pragma unroll
        for (int ks = 0; ks < 8; ks++) {
            const int col = ks*8 + t;
            unsigned a[4];
            a[0] = __float_as_uint(Qs[qr*APAD + col]);
            a[1] = __float_as_uint(Qs[(qr+8)*APAD + col]);
            a[2] = __float_as_uint(Qs[qr*APAD + col + 4]);
            a[3] = __float_as_uint(Qs[(qr+8)*APAD + col + 4]);
#pragma unroll
            for (int nf = 0; nf < 8; nf++) {
                unsigned bf[2];
                bf[0] = __float_as_uint(Ks[(nf*8+g)*APAD + col]);
                bf[1] = __float_as_uint(Ks[(nf*8+g)*APAD + col + 4]);
                mma8(sc[nf], a, bf);
            }
        }

#pragma unroll
        for (int nf = 0; nf < 8; nf++) {
#pragma unroll
            for (int ci = 0; ci < 2; ci++) {
                int jj = nf*8 + 2*t + ci;
                int j = j0 + jj;
                int jmv = jm[jj];
                bool ok0 = (j <= r0) && ((r0 - j < STRIDE) || (jmv == im0));
                bool ok1 = (j <= r1) && ((r1 - j < STRIDE) || (jmv == im1));
                sc[nf][ci]     = ok0 ? sc[nf][ci]     * 0.125f : -1e30f;
                sc[nf][2 + ci] = ok1 ? sc[nf][2 + ci] * 0.125f : -1e30f;
            }
        }

        float mx0 = -1e30f, mx1 = -1e30f;
#pragma unroll
        for (int nf = 0; nf < 8; nf++) {
            mx0 = fmaxf(mx0, fmaxf(sc[nf][0], sc[nf][1]));
            mx1 = fmaxf(mx1, fmaxf(sc[nf][2], sc[nf][3]));
        }
        mx0 = fmaxf(mx0, __shfl_xor_sync(0xffffffffu, mx0, 1));
        mx0 = fmaxf(mx0, __shfl_xor_sync(0xffffffffu, mx0, 2));
        mx1 = fmaxf(mx1, __shfl_xor_sync(0xffffffffu, mx1, 1));
        mx1 = fmaxf(mx1, __shfl_xor_sync(0xffffffffu, mx1, 2));
        float nm0 = fmaxf(m0r, mx0), nm1 = fmaxf(m1r, mx1);
        float al0 = __expf(m0r - nm0), al1 = __expf(m1r - nm1);
        float ps0 = 0.f, ps1 = 0.f;
#pragma unroll
        for (int nf = 0; nf < 8; nf++) {
            float p0 = __expf(sc[nf][0] - nm0); sc[nf][0] = p0; ps0 += p0;
            float p1 = __expf(sc[nf][1] - nm0); sc[nf][1] = p1; ps0 += p1;
            float p2 = __expf(sc[nf][2] - nm1); sc[nf][2] = p2; ps1 += p2;
            float p3 = __expf(sc[nf][3] - nm1); sc[nf][3] = p3; ps1 += p3;
        }
        ps0 += __shfl_xor_sync(0xffffffffu, ps0, 1);
        ps0 += __shfl_xor_sync(0xffffffffu, ps0, 2);
        ps1 += __shfl_xor_sync(0xffffffffu, ps1, 1);
        ps1 += __shfl_xor_sync(0xffffffffu, ps1, 2);
        m0r = nm0; m1r = nm1;
        l0 = l0*al0 + ps0;
        l1 = l1*al1 + ps1;
#pragma unroll
        for (int nf = 0; nf < 8; nf++) {
            o[nf][0] *= al0; o[nf][1] *= al0;
            o[nf][2] *= al1; o[nf][3] *= al1;
        }

        // stage P (tf32-rounded at store; rows warp-private)
#pragma unroll
        for (int nf = 0; nf < 8; nf++) {
            Ps[qr*APAD     + nf*8 + 2*t]     = rtf(sc[nf][0]);
            Ps[qr*APAD     + nf*8 + 2*t + 1] = rtf(sc[nf][1]);
            Ps[(qr+8)*APAD + nf*8 + 2*t]     = rtf(sc[nf][2]);
            Ps[(qr+8)*APAD + nf*8 + 2*t + 1] = rtf(sc[nf][3]);
        }
        __syncwarp();

#pragma unroll
        for (int ks = 0; ks < 8; ks++) {
            const int col = ks*8 + t;
            unsigned a[4];
            a[0] = __float_as_uint(Ps[qr*APAD + col]);
            a[1] = __float_as_uint(Ps[(qr+8)*APAD + col]);
            a[2] = __float_as_uint(Ps[qr*APAD + col + 4]);
            a[3] = __float_as_uint(Ps[(qr+8)*APAD + col + 4]);
#pragma unroll
            for (int nf = 0; nf < 8; nf++) {
                unsigned bf[2];
                bf[0] = __float_as_uint(Vs[col*APAD     + nf*8 + g]);
                bf[1] = __float_as_uint(Vs[(col+4)*APAD + nf*8 + g]);
                mma8(o[nf], a, bf);
            }
        }
        __syncwarp();
    }

    const float inv0 = 1.f / l0, inv1 = 1.f / l1;
#pragma unroll
    for (int nf = 0; nf < 8; nf++) {
        int d = h*HD + nf*8 + 2*t;
        *(float2*)&g_o[((size_t)b*SS + r0)*HH + d] =
            make_float2(rtf(o[nf][0]*inv0), rtf(o[nf][1]*inv0));
        *(float2*)&g_o[((size_t)b*SS + r1)*HH + d] =
            make_float2(rtf(o[nf][2]*inv1), rtf(o[nf][3]*inv1));
    }
}

// ---------------------------------------------------------------------------
// Fixed-head flash attention (heads 8..15) with column gathering.
// Valid columns for query tile [i0, i0+64):
//   summary cols j=45a+44 with j < bstart  (nsum = i0/45 of them)
//   contiguous [bstart, i0+63] where bstart = 45*(i0/45)
// ncols <= 152 -> at most 3 gathered K-tiles.
// ---------------------------------------------------------------------------
#define ATTN_SMEM_F ((4*64*APAD + 192) * 4)   // 70400 B

__global__ __launch_bounds__(128)
void attn_fixed()
{
    extern __shared__ float sm[];
    float* Qs = sm;
    float* Ks = sm + 64*APAD;
    float* Vs = sm + 2*64*APAD;
    float* Ps = sm + 3*64*APAD;
    int* jv = (int*)(sm + 4*64*APAD);
    int* jmt = jv + 64;
    int* jdt = jmt + 64;

    const int qt = blockIdx.x;
    const int h  = 8 + blockIdx.y;
    const int b  = blockIdx.z;
    const int i0 = qt * 64;

    const int nsum   = i0 / STRIDE;
    const int bstart = nsum * STRIDE;
    const int ncols  = nsum + (i0 + 64 - bstart);
    const int NT     = (ncols + 63) >> 6;

    const float* __restrict__ qb = g_q + (size_t)(b*NH + h) * SS * HD;
    const float* __restrict__ kb = g_k + (size_t)(b*NH + h) * SS * HD;
    const float* __restrict__ vb = g_v + (size_t)(b*NH + h) * SS * HD;

    const int tid = threadIdx.x;
    const int warp = tid >> 5, lane = tid & 31;
    const int g = lane >> 2, t = lane & 3;

#pragma unroll
    for (int i = 0; i < 8; i++) {
        int f = tid + i*128;
        int r = f >> 4, c4 = (f & 15) * 4;
        *(float4*)(Qs + r*APAD + c4) = *(const float4*)(qb + (size_t)(i0+r)*HD + c4);
    }

    const int r0 = i0 + warp*16 + g;
    const int r1 = r0 + 8;
    const int id0 = r0 / STRIDE, id1 = r1 / STRIDE;

    float o[8][4];
#pragma unroll
    for (int i = 0; i < 8; i++)
#pragma unroll
        for (int k = 0; k < 4; k++) o[i][k] = 0.f;
    float m0r = -1e30f, m1r = -1e30f, l0 = 0.f, l1 = 0.f;

    for (int ti = 0; ti < NT; ti++) {
        __syncthreads();
        // column tables for this gathered tile
        if (tid < 64) {
            int p = ti*64 + tid;
            int j = (p < ncols) ? ((p < nsum) ? (STRIDE*p + STRIDE-1)
                                              : (bstart + p - nsum))
                                : (1 << 28);
            jv[tid] = j;
            jmt[tid] = j % STRIDE;
            jdt[tid] = j / STRIDE;
        }
        // gathered K/V rows
#pragma unroll
        for (int i = 0; i < 8; i++) {
            int f = tid + i*128;
            int r = f >> 4, c4 = (f & 15) * 4;
            int p = ti*64 + r;
            int j = (p < ncols) ? ((p < nsum) ? (STRIDE*p + STRIDE-1)
                                              : (bstart + p - nsum)) : 0;
            *(float4*)(Ks + r*APAD + c4) = *(const float4*)(kb + (size_t)j*HD + c4);
            *(float4*)(Vs + r*APAD + c4) = *(const float4*)(vb + (size_t)j*HD + c4);
        }
        __syncthreads();

        float sc[8][4];
#pragma unroll
        for (int i = 0; i < 8; i++)
#pragma unroll
            for (int k = 0; k < 4; k++) sc[i][k] = 0.f;
        const int qr = warp*16 + g;
#pragma unroll
        for (int ks = 0; ks < 8; ks++) {
            const int col = ks*8 + t;
            unsigned a[4];
            a[0] = __float_as_uint(Qs[qr*APAD + col]);
            a[1] = __float_as_uint(Qs[(qr+8)*APAD + col]);
            a[2] = __float_as_uint(Qs[qr*APAD + col + 4]);
            a[3] = __float_as_uint(Qs[(qr+8)*APAD + col + 4]);
#pragma unroll
            for (int nf = 0; nf < 8; nf++) {
                unsigned bf[2];
                bf[0] = __float_as_uint(Ks[(nf*8+g)*APAD + col]);
                bf[1] = __float_as_uint(Ks[(nf*8+g)*APAD + col + 4]);
                mma8(sc[nf], a, bf);
            }
        }

        // fixed mask with real j
#pragma unroll
        for (int nf = 0; nf < 8; nf++) {
#pragma unroll
            for (int ci = 0; ci < 2; ci++) {
                int jj = nf*8 + 2*t + ci;
                int j = jv[jj];
                int jmv = jmt[jj], jdv = jdt[jj];
                bool ok0 = (j <= r0) && ((jdv == id0) || (jmv >= STRIDE - SUMC));
                bool ok1 = (j <= r1) && ((jdv == id1) || (jmv >= STRIDE - SUMC));
                sc[nf][ci]     = ok0 ? sc[nf][ci]     * 0.125f : -1e30f;
                sc[nf][2 + ci] = ok1 ? sc[nf][2 + ci] * 0.125f : -1e30f;
            }
        }

        float mx0 = -1e30f, mx1 = -1e30f;
#pragma unroll
        for (int nf = 0; nf < 8; nf++) {
            mx0 = fmaxf(mx0, fmaxf(sc[nf][0], sc[nf][1]));
            mx1 = fmaxf(mx1, fmaxf(sc[nf][2], sc[nf][3]));
        }
        mx0 = fmaxf(mx0, __shfl_xor_sync(0xffffffffu, mx0, 1));
        mx0 = fmaxf(mx0, __shfl_xor_sync(0xffffffffu, mx0, 2));
        mx1 = fmaxf(mx1, __shfl_xor_sync(0xffffffffu, mx1, 1));
        mx1 = fmaxf(mx1, __shfl_xor_sync(0xffffffffu, mx1, 2));
        float nm0 = fmaxf(m0r, mx0), nm1 = fmaxf(m1r, mx1);
        float al0 = __expf(m0r - nm0), al1 = __expf(m1r - nm1);
        float ps0 = 0.f, ps1 = 0.f;
#pragma unroll
        for (int nf = 0; nf < 8; nf++) {
            float p0 = __expf(sc[nf][0] - nm0); sc[nf][0] = p0; ps0 += p0;
            float p1 = __expf(sc[nf][1] - nm0); sc[nf][1] = p1; ps0 += p1;
            float p2 = __expf(sc[nf][2] - nm1); sc[nf][2] = p2; ps1 += p2;
            float p3 = __expf(sc[nf][3] - nm1); sc[nf][3] = p3; ps1 += p3;
        }
        ps0 += __shfl_xor_sync(0xffffffffu, ps0, 1);
        ps0 += __shfl_xor_sync(0xffffffffu, ps0, 2);
        ps1 += __shfl_xor_sync(0xffffffffu, ps1, 1);
        ps1 += __shfl_xor_sync(0xffffffffu, ps1, 2);
        m0r = nm0; m1r = nm1;
        l0 = l0*al0 + ps0;
        l1 = l1*al1 + ps1;
#pragma unroll
        for (int nf = 0; nf < 8; nf++) {
            o[nf][0] *= al0; o[nf][1] *= al0;
            o[nf][2] *= al1; o[nf][3] *= al1;
        }

#pragma unroll
        for (int nf = 0; nf < 8; nf++) {
            Ps[qr*APAD     + nf*8 + 2*t]     = rtf(sc[nf][0]);
            Ps[qr*APAD     + nf*8 + 2*t + 1] = rtf(sc[nf][1]);
            Ps[(qr+8)*APAD + nf*8 + 2*t]     = rtf(sc[nf][2]);
            Ps[(qr+8)*APAD + nf*8 + 2*t + 1] = rtf(sc[nf][3]);
        }
        __syncwarp();

#pragma unroll
        for (int ks = 0; ks < 8; ks++) {
            const int col = ks*8 + t;
            unsigned a[4];
            a[0] = __float_as_uint(Ps[qr*APAD + col]);
            a[1] = __float_as_uint(Ps[(qr+8)*APAD + col]);
            a[2] = __float_as_uint(Ps[qr*APAD + col + 4]);
            a[3] = __float_as_uint(Ps[(qr+8)*APAD + col + 4]);
#pragma unroll
            for (int nf = 0; nf < 8; nf++) {
                unsigned bf[2];
                bf[0] = __float_as_uint(Vs[col*APAD     + nf*8 + g]);
                bf[1] = __float_as_uint(Vs[(col+4)*APAD + nf*8 + g]);
                mma8(o[nf], a, bf);
            }
        }
        __syncwarp();
    }

    const float inv0 = 1.f / l0, inv1 = 1.f / l1;
#pragma unroll
    for (int nf = 0; nf < 8; nf++) {
        int d = h*HD + nf*8 + 2*t;
        *(float2*)&g_o[((size_t)b*SS + r0)*HH + d] =
            make_float2(rtf(o[nf][0]*inv0), rtf(o[nf][1]*inv0));
        *(float2*)&g_o[((size_t)b*SS + r1)*HH + d] =
            make_float2(rtf(o[nf][2]*inv1), rtf(o[nf][3]*inv1));
    }
}

// ---------------------------------------------------------------------------
// Output projection, tf32 mma, pre-rounded operands.
// ---------------------------------------------------------------------------
__global__ __launch_bounds__(256, 2)
void oproj_mma(float* __restrict__ out)
{
    extern __shared__ float sm[];
    float* Abuf[2] = { sm,            sm + 128*RP   };
    float* Bbuf[2] = { sm + 2*128*RP, sm + 3*128*RP };

    const int n0 = blockIdx.x * 128;
    const int m0 = blockIdx.y * 128;

    const int tid  = threadIdx.x;
    const int warp = tid >> 5;
    const int lane = tid & 31;
    const int g = lane >> 2;
    const int t = lane & 3;
    const int wm = warp >> 2;
    const int wn = warp & 3;

    float c[4][4][4];
#pragma unroll
    for (int i = 0; i < 4; i++)
#pragma unroll
        for (int j = 0; j < 4; j++)
#pragma unroll
            for (int k = 0; k < 4; k++) c[i][j][k] = 0.f;

#pragma unroll
    for (int i = 0; i < 4; i++) {
        int f = tid + i*256;
        int r = f >> 3, c4 = (f & 7) * 4;
        cpa16(Abuf[0] + r*RP + c4, g_o  + (size_t)(m0+r)*HH + c4);
        cpa16(Bbuf[0] + r*RP + c4, g_wot + (size_t)(n0+r)*HH + c4);
    }
    asm volatile("cp.async.commit_group;");

    const int NT = HH / 32;
    for (int ti = 0; ti < NT; ti++) {
        asm volatile("cp.async.wait_group 0;");
        __syncthreads();
        const int cur = ti & 1;
        if (ti + 1 < NT) {
            const int k0 = (ti+1) * 32;
            const int nxt = cur ^ 1;
#pragma unroll
            for (int i = 0; i < 4; i++) {
                int f = tid + i*256;
                int r = f >> 3, c4 = (f & 7) * 4;
                cpa16(Abuf[nxt] + r*RP + c4, g_o  + (size_t)(m0+r)*HH + k0 + c4);
                cpa16(Bbuf[nxt] + r*RP + c4, g_wot + (size_t)(n0+r)*HH + k0 + c4);
            }
            asm volatile("cp.async.commit_group;");
        }
        const float* As = Abuf[cur];
        const float* Bs = Bbuf[cur];
#pragma unroll
        for (int ks = 0; ks < 4; ks++) {
            const int col = ks*8 + t;
            unsigned a[4][4], b[4][2];
#pragma unroll
            for (int mf = 0; mf < 4; mf++) {
                int r = wm*64 + mf*16 + g;
                a[mf][0] = __float_as_uint(As[r*RP + col]);
                a[mf][1] = __float_as_uint(As[(r+8)*RP + col]);
                a[mf][2] = __float_as_uint(As[r*RP + col + 4]);
                a[mf][3] = __float_as_uint(As[(r+8)*RP + col + 4]);
            }
#pragma unroll
            for (int nf = 0; nf < 4; nf++) {
                int n = wn*32 + nf*8 + g;
                b[nf][0] = __float_as_uint(Bs[n*RP + col]);
                b[nf][1] = __float_as_uint(Bs[n*RP + col + 4]);
            }
#pragma unroll
            for (int mf = 0; mf < 4; mf++)
#pragma unroll
                for (int nf = 0; nf < 4; nf++)
                    mma8(c[mf][nf], a[mf], b[nf]);
        }
        __syncthreads();
    }

#pragma unroll
    for (int mf = 0; mf < 4; mf++) {
#pragma unroll
        for (int half = 0; half < 2; half++) {
            int m = m0 + wm*64 + mf*16 + g + half*8;
#pragma unroll
            for (int nf = 0; nf < 4; nf++) {
                int n = n0 + wn*32 + nf*8 + 2*t;
                float2 v2 = half ? make_float2(c[mf][nf][2], c[mf][nf][3])
                                 : make_float2(c[mf][nf][0], c[mf][nf][1]);
                *(float2*)&out[(size_t)m*HH + n] = v2;
            }
        }
    }
}

// ---------------------------------------------------------------------------
extern "C" void kernel_launch(void* const* d_in, const int* in_sizes, int n_in,
                              void* d_out, int out_size)
{
    const float* x  = (const float*)d_in[0];
    const float* Wq = (const float*)d_in[1];
    const float* Wk = (const float*)d_in[2];
    const float* Wv = (const float*)d_in[3];
    const float* Wo = (const float*)d_in[4];
    float* out = (float*)d_out;

    cudaFuncSetAttribute(qkv_mma,      cudaFuncAttributeMaxDynamicSharedMemorySize, GEMM_SMEM);
    cudaFuncSetAttribute(attn_strided, cudaFuncAttributeMaxDynamicSharedMemorySize, ATTN_SMEM);
    cudaFuncSetAttribute(attn_fixed,   cudaFuncAttributeMaxDynamicSharedMemorySize, ATTN_SMEM_F);
    cudaFuncSetAttribute(oproj_mma,    cudaFuncAttributeMaxDynamicSharedMemorySize, GEMM_SMEM);

    precvt<<<(XF4 + 4*WF4 + 255)/256, 256>>>(x, Wq, Wk, Wv, Wo);
    qkv_mma<<<dim3(24, 32), 256, GEMM_SMEM>>>();
    attn_strided<<<dim3(SS/64, NH/2, BB), 128, ATTN_SMEM>>>();
    attn_fixed  <<<dim3(SS/64, NH/2, BB), 128, ATTN_SMEM_F>>>();
    oproj_mma<<<dim3(8, 32), 256, GEMM_SMEM>>>(out);
}

// round 7
// speedup vs baseline: 4.4918x; 1.3172x over previous
#include <cuda_runtime.h>
#include <math.h>

// Problem constants
#define BB 2
#define SS 2048
#define HH 1024
#define NH 16
#define HD 64
#define MM (BB*SS)
#define STRIDE 45
#define SUMC 1

// Scratch (device globals: allocation-free per harness rules)
__device__ float g_q[BB*NH*SS*HD];   // [B, nh, S, hd]  (tf32-rounded)
__device__ float g_k[BB*NH*SS*HD];
__device__ float g_v[BB*NH*SS*HD];
__device__ float g_o[BB*SS*HH];      // attention out, [B, S, H] (tf32-rounded)
__device__ float g_xt[MM*HH];        // tf32-rounded inputs/weights
__device__ float g_wt[3*HH*HH];      // Wq, Wk, Wv
__device__ float g_wot[HH*HH];
// strided-head split-softmax partials: [B, 8, S, HD] unnormalized o; [B,8,S] m,l
__device__ float g_oA[BB*8*SS*HD];
__device__ float g_oB[BB*8*SS*HD];
__device__ float g_mA[BB*8*SS];
__device__ float g_lA[BB*8*SS];
__device__ float g_mB[BB*8*SS];
__device__ float g_lB[BB*8*SS];

// ---------------------------------------------------------------------------
// helpers
// ---------------------------------------------------------------------------
__device__ __forceinline__ unsigned f2tf(float x) {
    unsigned u; asm("cvt.rna.tf32.f32 %0, %1;" : "=r"(u) : "f"(x)); return u;
}
__device__ __forceinline__ float rtf(float x) { return __uint_as_float(f2tf(x)); }
__device__ __forceinline__ void mma8(float c[4], const unsigned a[4], const unsigned b[2]) {
    asm volatile("mma.sync.aligned.m16n8k8.row.col.f32.tf32.tf32.f32 "
        "{%0,%1,%2,%3}, {%4,%5,%6,%7}, {%8,%9}, {%0,%1,%2,%3};"
        : "+f"(c[0]), "+f"(c[1]), "+f"(c[2]), "+f"(c[3])
        : "r"(a[0]), "r"(a[1]), "r"(a[2]), "r"(a[3]), "r"(b[0]), "r"(b[1]));
}
__device__ __forceinline__ void cpa16(float* s, const float* g) {
    unsigned sa = (unsigned)__cvta_generic_to_shared(s);
    asm volatile("cp.async.cg.shared.global [%0], [%1], 16;" :: "r"(sa), "l"(g));
}

// ---------------------------------------------------------------------------
// Prologue: round x / Wq / Wk / Wv / Wo to tf32 (stored as f32 bits).
// ---------------------------------------------------------------------------
#define XF4 (MM*HH/4)      // 1048576
#define WF4 (HH*HH/4)      // 262144

__global__ __launch_bounds__(256)
void precvt(const float* __restrict__ x,  const float* __restrict__ Wq,
            const float* __restrict__ Wk, const float* __restrict__ Wv,
            const float* __restrict__ Wo)
{
    int i = blockIdx.x * 256 + threadIdx.x;
    const float4* s; float4* d; int k;
    if (i < XF4) { s = (const float4*)x; d = (float4*)g_xt; k = i; }
    else {
        int w = (i - XF4) >> 18;           // / WF4
        k = (i - XF4) & (WF4 - 1);
        const float* srcs[4] = { Wq, Wk, Wv, Wo };
        s = (const float4*)srcs[w];
        d = (w < 3) ? (float4*)(g_wt + (size_t)w*HH*HH) : (float4*)g_wot;
    }
    float4 v = s[k];
    v.x = rtf(v.x); v.y = rtf(v.y); v.z = rtf(v.z); v.w = rtf(v.w);
    d[k] = v;
}

// ---------------------------------------------------------------------------
// QKV projection, tf32 mma, pre-rounded operands (no in-loop cvt).
// ---------------------------------------------------------------------------
#define RP 36
#define GEMM_SMEM (4*128*RP*4)  // 73728 B

__global__ __launch_bounds__(256, 2)
void qkv_mma()
{
    extern __shared__ float sm[];
    float* Abuf[2] = { sm,            sm + 128*RP   };
    float* Bbuf[2] = { sm + 2*128*RP, sm + 3*128*RP };

    const int sel = blockIdx.x >> 3;
    const float* __restrict__ W = g_wt + (size_t)sel*HH*HH;
    const float* __restrict__ x = g_xt;
    const int n0 = (blockIdx.x & 7) * 128;
    const int m0 = blockIdx.y * 128;

    const int tid  = threadIdx.x;
    const int warp = tid >> 5;
    const int lane = tid & 31;
    const int g = lane >> 2;
    const int t = lane & 3;
    const int wm = warp >> 2;
    const int wn = warp & 3;

    float c[4][4][4];
#pragma unroll
    for (int i = 0; i < 4; i++)
#pragma unroll
        for (int j = 0; j < 4; j++)
#pragma unroll
            for (int k = 0; k < 4; k++) c[i][j][k] = 0.f;

#pragma unroll
    for (int i = 0; i < 4; i++) {
        int f = tid + i*256;
        int r = f >> 3, c4 = (f & 7) * 4;
        cpa16(Abuf[0] + r*RP + c4, x + (size_t)(m0+r)*HH + c4);
        cpa16(Bbuf[0] + r*RP + c4, W + (size_t)(n0+r)*HH + c4);
    }
    asm volatile("cp.async.commit_group;");

    const int NT = HH / 32;
    for (int ti = 0; ti < NT; ti++) {
        asm volatile("cp.async.wait_group 0;");
        __syncthreads();
        const int cur = ti & 1;
        if (ti + 1 < NT) {
            const int k0 = (ti+1) * 32;
            const int nxt = cur ^ 1;
#pragma unroll
            for (int i = 0; i < 4; i++) {
                int f = tid + i*256;
                int r = f >> 3, c4 = (f & 7) * 4;
                cpa16(Abuf[nxt] + r*RP + c4, x + (size_t)(m0+r)*HH + k0 + c4);
                cpa16(Bbuf[nxt] + r*RP + c4, W + (size_t)(n0+r)*HH + k0 + c4);
            }
            asm volatile("cp.async.commit_group;");
        }
        const float* As = Abuf[cur];
        const float* Bs = Bbuf[cur];
#pragma unroll
        for (int ks = 0; ks < 4; ks++) {
            const int col = ks*8 + t;
            unsigned a[4][4], b[4][2];
#pragma unroll
            for (int mf = 0; mf < 4; mf++) {
                int r = wm*64 + mf*16 + g;
                a[mf][0] = __float_as_uint(As[r*RP + col]);
                a[mf][1] = __float_as_uint(As[(r+8)*RP + col]);
                a[mf][2] = __float_as_uint(As[r*RP + col + 4]);
                a[mf][3] = __float_as_uint(As[(r+8)*RP + col + 4]);
            }
#pragma unroll
            for (int nf = 0; nf < 4; nf++) {
                int n = wn*32 + nf*8 + g;
                b[nf][0] = __float_as_uint(Bs[n*RP + col]);
                b[nf][1] = __float_as_uint(Bs[n*RP + col + 4]);
            }
#pragma unroll
            for (int mf = 0; mf < 4; mf++)
#pragma unroll
                for (int nf = 0; nf < 4; nf++)
                    mma8(c[mf][nf], a[mf], b[nf]);
        }
        __syncthreads();
    }

    float* dst = (sel == 0) ? g_q : (sel == 1) ? g_k : g_v;
#pragma unroll
    for (int mf = 0; mf < 4; mf++) {
#pragma unroll
        for (int half = 0; half < 2; half++) {
            int m = m0 + wm*64 + mf*16 + g + half*8;
            int bb = m >> 11, s = m & 2047;
#pragma unroll
            for (int nf = 0; nf < 4; nf++) {
                int n = n0 + wn*32 + nf*8 + 2*t;
                int h = n >> 6, d = n & 63;
                float2 v2 = half ? make_float2(c[mf][nf][2], c[mf][nf][3])
                                 : make_float2(c[mf][nf][0], c[mf][nf][1]);
                v2.x = rtf(v2.x); v2.y = rtf(v2.y);
                *(float2*)&dst[(((size_t)(bb*NH + h))*SS + s)*HD + d] = v2;
            }
        }
    }
}

// ---------------------------------------------------------------------------
// Strided heads, part A: window columns [max(0,i0-44), i0+64) (<=108 cols,
// <=2 K-tiles) with the FULL strided mask. Writes unnormalized partials.
// ---------------------------------------------------------------------------
#define APAD 68
#define ATTN_SMEM_W ((4*64*APAD + 128) * 4)

__global__ __launch_bounds__(128)
void attn_win()
{
    extern __shared__ float sm[];
    float* Qs = sm;
    float* Ks = sm + 64*APAD;
    float* Vs = sm + 2*64*APAD;
    float* Ps = sm + 3*64*APAD;
    int* jv = (int*)(sm + 4*64*APAD);
    int* jm = jv + 64;

    const int qt = blockIdx.x, h = blockIdx.y, b = blockIdx.z;
    const int i0 = qt * 64;
    const int lo = (i0 >= 44) ? i0 - 44 : 0;
    const int ncols = i0 + 64 - lo;
    const int NT = (ncols + 63) >> 6;

    const float* __restrict__ qb = g_q + (size_t)(b*NH + h) * SS * HD;
    const float* __restrict__ kb = g_k + (size_t)(b*NH + h) * SS * HD;
    const float* __restrict__ vb = g_v + (size_t)(b*NH + h) * SS * HD;

    const int tid = threadIdx.x;
    const int warp = tid >> 5, lane = tid & 31;
    const int g = lane >> 2, t = lane & 3;

#pragma unroll
    for (int i = 0; i < 8; i++) {
        int f = tid + i*128;
        int r = f >> 4, c4 = (f & 15) * 4;
        *(float4*)(Qs + r*APAD + c4) = *(const float4*)(qb + (size_t)(i0+r)*HD + c4);
    }

    const int r0 = i0 + warp*16 + g;
    const int r1 = r0 + 8;
    const int im0 = r0 % STRIDE, im1 = r1 % STRIDE;

    float o[8][4];
#pragma unroll
    for (int i = 0; i < 8; i++)
#pragma unroll
        for (int k = 0; k < 4; k++) o[i][k] = 0.f;
    float m0r = -1e30f, m1r = -1e30f, l0 = 0.f, l1 = 0.f;

    for (int ti = 0; ti < NT; ti++) {
        __syncthreads();
        if (tid < 64) {
            int p = ti*64 + tid;
            int j = (p < ncols) ? (lo + p) : (1 << 28);
            jv[tid] = j;
            jm[tid] = (lo + p) % STRIDE;
        }
#pragma unroll
        for (int i = 0; i < 8; i++) {
            int f = tid + i*128;
            int r = f >> 4, c4 = (f & 15) * 4;
            int p = ti*64 + r;
            int j = (p < ncols) ? (lo + p) : lo;
            *(float4*)(Ks + r*APAD + c4) = *(const float4*)(kb + (size_t)j*HD + c4);
            *(float4*)(Vs + r*APAD + c4) = *(const float4*)(vb + (size_t)j*HD + c4);
        }
        __syncthreads();

        float sc[8][4];
#pragma unroll
        for (int i = 0; i < 8; i++)
#pragma unroll
            for (int k = 0; k < 4; k++) sc[i][k] = 0.f;
        const int qr = warp*16 + g;
#pragma unroll
        for (int ks = 0; ks < 8; ks++) {
            const int col = ks*8 + t;
            unsigned a[4];
            a[0] = __float_as_uint(Qs[qr*APAD + col]);
            a[1] = __float_as_uint(Qs[(qr+8)*APAD + col]);
            a[2] = __float_as_uint(Qs[qr*APAD + col + 4]);
            a[3] = __float_as_uint(Qs[(qr+8)*APAD + col + 4]);
#pragma unroll
            for (int nf = 0; nf < 8; nf++) {
                unsigned bf[2];
                bf[0] = __float_as_uint(Ks[(nf*8+g)*APAD + col]);
                bf[1] = __float_as_uint(Ks[(nf*8+g)*APAD + col + 4]);
                mma8(sc[nf], a, bf);
            }
        }

#pragma unroll
        for (int nf = 0; nf < 8; nf++) {
#pragma unroll
            for (int ci = 0; ci < 2; ci++) {
                int jj = nf*8 + 2*t + ci;
                int j = jv[jj];
                int jmv = jm[jj];
                bool ok0 = (j <= r0) && ((r0 - j < STRIDE) || (jmv == im0));
                bool ok1 = (j <= r1) && ((r1 - j < STRIDE) || (jmv == im1));
                sc[nf][ci]     = ok0 ? sc[nf][ci]     * 0.125f : -1e30f;
                sc[nf][2 + ci] = ok1 ? sc[nf][2 + ci] * 0.125f : -1e30f;
            }
        }

        float mx0 = -1e30f, mx1 = -1e30f;
#pragma unroll
        for (int nf = 0; nf < 8; nf++) {
            mx0 = fmaxf(mx0, fmaxf(sc[nf][0], sc[nf][1]));
            mx1 = fmaxf(mx1, fmaxf(sc[nf][2], sc[nf][3]));
        }
        mx0 = fmaxf(mx0, __shfl_xor_sync(0xffffffffu, mx0, 1));
        mx0 = fmaxf(mx0, __shfl_xor_sync(0xffffffffu, mx0, 2));
        mx1 = fmaxf(mx1, __shfl_xor_sync(0xffffffffu, mx1, 1));
        mx1 = fmaxf(mx1, __shfl_xor_sync(0xffffffffu, mx1, 2));
        float nm0 = fmaxf(m0r, mx0), nm1 = fmaxf(m1r, mx1);
        float al0 = __expf(m0r - nm0), al1 = __expf(m1r - nm1);
        float ps0 = 0.f, ps1 = 0.f;
#pragma unroll
        for (int nf = 0; nf < 8; nf++) {
            float p0 = __expf(sc[nf][0] - nm0); sc[nf][0] = p0; ps0 += p0;
            float p1 = __expf(sc[nf][1] - nm0); sc[nf][1] = p1; ps0 += p1;
            float p2 = __expf(sc[nf][2] - nm1); sc[nf][2] = p2; ps1 += p2;
            float p3 = __expf(sc[nf][3] - nm1); sc[nf][3] = p3; ps1 += p3;
        }
        ps0 += __shfl_xor_sync(0xffffffffu, ps0, 1);
        ps0 += __shfl_xor_sync(0xffffffffu, ps0, 2);
        ps1 += __shfl_xor_sync(0xffffffffu, ps1, 1);
        ps1 += __shfl_xor_sync(0xffffffffu, ps1, 2);
        m0r = nm0; m1r = nm1;
        l0 = l0*al0 + ps0;
        l1 = l1*al1 + ps1;
#pragma unroll
        for (int nf = 0; nf < 8; nf++) {
            o[nf][0] *= al0; o[nf][1] *= al0;
            o[nf][2] *= al1; o[nf][3] *= al1;
        }

#pragma unroll
        for (int nf = 0; nf < 8; nf++) {
            Ps[qr*APAD     + nf*8 + 2*t]     = rtf(sc[nf][0]);
            Ps[qr*APAD     + nf*8 + 2*t + 1] = rtf(sc[nf][1]);
            Ps[(qr+8)*APAD + nf*8 + 2*t]     = rtf(sc[nf][2]);
            Ps[(qr+8)*APAD + nf*8 + 2*t + 1] = rtf(sc[nf][3]);
        }
        __syncwarp();

#pragma unroll
        for (int ks = 0; ks < 8; ks++) {
            const int col = ks*8 + t;
            unsigned a[4];
            a[0] = __float_as_uint(Ps[qr*APAD + col]);
            a[1] = __float_as_uint(Ps[(qr+8)*APAD + col]);
            a[2] = __float_as_uint(Ps[qr*APAD + col + 4]);
            a[3] = __float_as_uint(Ps[(qr+8)*APAD + col + 4]);
#pragma unroll
            for (int nf = 0; nf < 8; nf++) {
                unsigned bf[2];
                bf[0] = __float_as_uint(Vs[col*APAD     + nf*8 + g]);
                bf[1] = __float_as_uint(Vs[(col+4)*APAD + nf*8 + g]);
                mma8(o[nf], a, bf);
            }
        }
        __syncwarp();
    }

    // write unnormalized partials
    const size_t rowbase = ((size_t)(b*8 + h)) * SS;
#pragma unroll
    for (int nf = 0; nf < 8; nf++) {
        int d = nf*8 + 2*t;
        *(float2*)&g_oA[(rowbase + r0)*HD + d] = make_float2(o[nf][0], o[nf][1]);
        *(float2*)&g_oA[(rowbase + r1)*HD + d] = make_float2(o[nf][2], o[nf][3]);
    }
    if (t == 0) {
        g_mA[rowbase + r0] = m0r; g_lA[rowbase + r0] = l0;
        g_mA[rowbase + r1] = m1r; g_lA[rowbase + r1] = l1;
    }
}

// ---------------------------------------------------------------------------
// Strided heads, part B: residue-grouped columns. Block = (b, h, residue r).
// Q rows: i = r + 45p (p < Nq <= 46). K cols: j = r + 45p'.
// Valid iff j < max(0, (i/64)*64 - 44)  (exactly the columns part A skipped).
// Single 64x64 tile. Writes unnormalized partials.
// ---------------------------------------------------------------------------
__global__ __launch_bounds__(128)
void attn_res()
{
    extern __shared__ float sm[];
    float* Qs = sm;
    float* Ks = sm + 64*APAD;
    float* Vs = sm + 2*64*APAD;
    float* Ps = sm + 3*64*APAD;

    const int r  = blockIdx.x;          // residue 0..44
    const int h  = blockIdx.y;          // strided head 0..7
    const int b  = blockIdx.z;

    const float* __restrict__ qb = g_q + (size_t)(b*NH + h) * SS * HD;
    const float* __restrict__ kb = g_k + (size_t)(b*NH + h) * SS * HD;
    const float* __restrict__ vb = g_v + (size_t)(b*NH + h) * SS * HD;

    const int tid = threadIdx.x;
    const int warp = tid >> 5, lane = tid & 31;
    const int g = lane >> 2, t = lane & 3;

    // gathered Q/K/V (clamped rows are fully masked)
#pragma unroll
    for (int i = 0; i < 8; i++) {
        int f = tid + i*128;
        int p = f >> 4, c4 = (f & 15) * 4;
        int iq = r + STRIDE*p; if (iq >= SS) iq = 0;
        *(float4*)(Qs + p*APAD + c4) = *(const float4*)(qb + (size_t)iq*HD + c4);
        *(float4*)(Ks + p*APAD + c4) = *(const float4*)(kb + (size_t)iq*HD + c4);
        *(float4*)(Vs + p*APAD + c4) = *(const float4*)(vb + (size_t)iq*HD + c4);
    }
    __syncthreads();

    const int p0 = warp*16 + g;         // row indices in gathered space
    const int p1 = p0 + 8;
    const int i0r = r + STRIDE*p0;      // real sequence rows (may be >= SS)
    const int i1r = r + STRIDE*p1;
    const int lo0 = (i0r < SS) ? max(0, ((i0r >> 6) << 6) - 44) : 0;
    const int lo1 = (i1r < SS) ? max(0, ((i1r >> 6) << 6) - 44) : 0;

    float sc[8][4];
#pragma unroll
    for (int i = 0; i < 8; i++)
#pragma unroll
        for (int k = 0; k < 4; k++) sc[i][k] = 0.f;
#pragma unroll
    for (int ks = 0; ks < 8; ks++) {
        const int col = ks*8 + t;
        unsigned a[4];
        a[0] = __float_as_uint(Qs[p0*APAD + col]);
        a[1] = __float_as_uint(Qs[p1*APAD + col]);
        a[2] = __float_as_uint(Qs[p0*APAD + col + 4]);
        a[3] = __float_as_uint(Qs[p1*APAD + col + 4]);
#pragma unroll
        for (int nf = 0; nf < 8; nf++) {
            unsigned bf[2];
            bf[0] = __float_as_uint(Ks[(nf*8+g)*APAD + col]);
            bf[1] = __float_as_uint(Ks[(nf*8+g)*APAD + col + 4]);
            mma8(sc[nf], a, bf);
        }
    }

    // mask: j = r + 45*colidx must satisfy j < lo(i)
#pragma unroll
    for (int nf = 0; nf < 8; nf++) {
#pragma unroll
        for (int ci = 0; ci < 2; ci++) {
            int jj = nf*8 + 2*t + ci;
            int j = r + STRIDE*jj;
            sc[nf][ci]     = (j < lo0) ? sc[nf][ci]     * 0.125f : -1e30f;
            sc[nf][2 + ci] = (j < lo1) ? sc[nf][2 + ci] * 0.125f : -1e30f;
        }
    }

    // single-pass softmax with explicit zero for masked entries
    float mx0 = -1e30f, mx1 = -1e30f;
#pragma unroll
    for (int nf = 0; nf < 8; nf++) {
        mx0 = fmaxf(mx0, fmaxf(sc[nf][0], sc[nf][1]));
        mx1 = fmaxf(mx1, fmaxf(sc[nf][2], sc[nf][3]));
    }
    mx0 = fmaxf(mx0, __shfl_xor_sync(0xffffffffu, mx0, 1));
    mx0 = fmaxf(mx0, __shfl_xor_sync(0xffffffffu, mx0, 2));
    mx1 = fmaxf(mx1, __shfl_xor_sync(0xffffffffu, mx1, 1));
    mx1 = fmaxf(mx1, __shfl_xor_sync(0xffffffffu, mx1, 2));
    float ps0 = 0.f, ps1 = 0.f;
#pragma unroll
    for (int nf = 0; nf < 8; nf++) {
        float p0v = (sc[nf][0] > -5e29f) ? __expf(sc[nf][0] - mx0) : 0.f; sc[nf][0] = p0v; ps0 += p0v;
        float p1v = (sc[nf][1] > -5e29f) ? __expf(sc[nf][1] - mx0) : 0.f; sc[nf][1] = p1v; ps0 += p1v;
        float p2v = (sc[nf][2] > -5e29f) ? __expf(sc[nf][2] - mx1) : 0.f; sc[nf][2] = p2v; ps1 += p2v;
        float p3v = (sc[nf][3] > -5e29f) ? __expf(sc[nf][3] - mx1) : 0.f; sc[nf][3] = p3v; ps1 += p3v;
    }
    ps0 += __shfl_xor_sync(0xffffffffu, ps0, 1);
    ps0 += __shfl_xor_sync(0xffffffffu, ps0, 2);
    ps1 += __shfl_xor_sync(0xffffffffu, ps1, 1);
    ps1 += __shfl_xor_sync(0xffffffffu, ps1, 2);

#pragma unroll
    for (int nf = 0; nf < 8; nf++) {
        Ps[p0*APAD + nf*8 + 2*t]     = rtf(sc[nf][0]);
        Ps[p0*APAD + nf*8 + 2*t + 1] = rtf(sc[nf][1]);
        Ps[p1*APAD + nf*8 + 2*t]     = rtf(sc[nf][2]);
        Ps[p1*APAD + nf*8 + 2*t + 1] = rtf(sc[nf][3]);
    }
    __syncwarp();

    float o[8][4];
#pragma unroll
    for (int i = 0; i < 8; i++)
#pragma unroll
        for (int k = 0; k < 4; k++) o[i][k] = 0.f;
#pragma unroll
    for (int ks = 0; ks < 8; ks++) {
        const int col = ks*8 + t;
        unsigned a[4];
        a[0] = __float_as_uint(Ps[p0*APAD + col]);
        a[1] = __float_as_uint(Ps[p1*APAD + col]);
        a[2] = __float_as_uint(Ps[p0*APAD + col + 4]);
        a[3] = __float_as_uint(Ps[p1*APAD + col + 4]);
#pragma unroll
        for (int nf = 0; nf < 8; nf++) {
            unsigned bf[2];
            bf[0] = __float_as_uint(Vs[col*APAD     + nf*8 + g]);
            bf[1] = __float_as_uint(Vs[(col+4)*APAD + nf*8 + g]);
            mma8(o[nf], a, bf);
        }
    }
    __syncwarp();

    const size_t rowbase = ((size_t)(b*8 + h)) * SS;
    if (i0r < SS) {
#pragma unroll
        for (int nf = 0; nf < 8; nf++) {
            int d = nf*8 + 2*t;
            *(float2*)&g_oB[(rowbase + i0r)*HD + d] = make_float2(o[nf][0], o[nf][1]);
        }
        if (t == 0) { g_mB[rowbase + i0r] = mx0; g_lB[rowbase + i0r] = ps0; }
    }
    if (i1r < SS) {
#pragma unroll
        for (int nf = 0; nf < 8; nf++) {
            int d = nf*8 + 2*t;
            *(float2*)&g_oB[(rowbase + i1r)*HD + d] = make_float2(o[nf][2], o[nf][3]);
        }
        if (t == 0) { g_mB[rowbase + i1r] = mx1; g_lB[rowbase + i1r] = ps1; }
    }
}

// ---------------------------------------------------------------------------
// Merge A + B partials for strided heads -> g_o (tf32-rounded).
// One thread = one float4 of head-dim. 2*8*2048*16 threads.
// ---------------------------------------------------------------------------
__global__ __launch_bounds__(256)
void attn_merge()
{
    int idx = blockIdx.x * 256 + threadIdx.x;   // < 524288
    int d4 = idx & 15;
    int i  = (idx >> 4) & 2047;
    int h  = (idx >> 15) & 7;
    int b  = idx >> 18;
    size_t row = ((size_t)(b*8 + h)) * SS + i;

    float mA = g_mA[row], lA = g_lA[row];
    float mB = g_mB[row], lB = g_lB[row];
    float m = fmaxf(mA, mB);
    float eA = __expf(mA - m), eB = __expf(mB - m);
    float L = lA*eA + lB*eB;
    float inv = 1.f / L;

    float4 a = *(const float4*)&g_oA[row*HD + d4*4];
    float4 c = *(const float4*)&g_oB[row*HD + d4*4];
    float4 o;
    o.x = rtf((a.x*eA + c.x*eB) * inv);
    o.y = rtf((a.y*eA + c.y*eB) * inv);
    o.z = rtf((a.z*eA + c.z*eB) * inv);
    o.w = rtf((a.w*eA + c.w*eB) * inv);
    *(float4*)&g_o[((size_t)b*SS + i)*HH + h*HD + d4*4] = o;
}

// ---------------------------------------------------------------------------
// Fixed-head flash attention (heads 8..15) with column gathering (unchanged).
// ---------------------------------------------------------------------------
#define ATTN_SMEM_F ((4*64*APAD + 192) * 4)

__global__ __launch_bounds__(128)
void attn_fixed()
{
    extern __shared__ float sm[];
    float* Qs = sm;
    float* Ks = sm + 64*APAD;
    float* Vs = sm + 2*64*APAD;
    float* Ps = sm + 3*64*APAD;
    int* jv = (int*)(sm + 4*64*APAD);
    int* jmt = jv + 64;
    int* jdt = jmt + 64;

    const int qt = blockIdx.x;
    const int h  = 8 + blockIdx.y;
    const int b  = blockIdx.z;
    const int i0 = qt * 64;

    const int nsum   = i0 / STRIDE;
    const int bstart = nsum * STRIDE;
    const int ncols  = nsum + (i0 + 64 - bstart);
    const int NT     = (ncols + 63) >> 6;

    const float* __restrict__ qb = g_q + (size_t)(b*NH + h) * SS * HD;
    const float* __restrict__ kb = g_k + (size_t)(b*NH + h) * SS * HD;
    const float* __restrict__ vb = g_v + (size_t)(b*NH + h) * SS * HD;

    const int tid = threadIdx.x;
    const int warp = tid >> 5, lane = tid & 31;
    const int g = lane >> 2, t = lane & 3;

#pragma unroll
    for (int i = 0; i < 8; i++) {
        int f = tid + i*128;
        int r = f >> 4, c4 = (f & 15) * 4;
        *(float4*)(Qs + r*APAD + c4) = *(const float4*)(qb + (size_t)(i0+r)*HD + c4);
    }

    const int r0 = i0 + warp*16 + g;
    const int r1 = r0 + 8;
    const int id0 = r0 / STRIDE, id1 = r1 / STRIDE;

    float o[8][4];
#pragma unroll
    for (int i = 0; i < 8; i++)
#pragma unroll
        for (int k = 0; k < 4; k++) o[i][k] = 0.f;
    float m0r = -1e30f, m1r = -1e30f, l0 = 0.f, l1 = 0.f;

    for (int ti = 0; ti < NT; ti++) {
        __syncthreads();
        if (tid < 64) {
            int p = ti*64 + tid;
            int j = (p < ncols) ? ((p < nsum) ? (STRIDE*p + STRIDE-1)
                                              : (bstart + p - nsum))
                                : (1 << 28);
            jv[tid] = j;
            jmt[tid] = j % STRIDE;
            jdt[tid] = j / STRIDE;
        }
#pragma unroll
        for (int i = 0; i < 8; i++) {
            int f = tid + i*128;
            int r = f >> 4, c4 = (f & 15) * 4;
            int p = ti*64 + r;
            int j = (p < ncols) ? ((p < nsum) ? (STRIDE*p + STRIDE-1)
                                              : (bstart + p - nsum)) : 0;
            *(float4*)(Ks + r*APAD + c4) = *(const float4*)(kb + (size_t)j*HD + c4);
            *(float4*)(Vs + r*APAD + c4) = *(const float4*)(vb + (size_t)j*HD + c4);
        }
        __syncthreads();

        float sc[8][4];
#pragma unroll
        for (int i = 0; i < 8; i++)
#pragma unroll
            for (int k = 0; k < 4; k++) sc[i][k] = 0.f;
        const int qr = warp*16 + g;
#pragma unroll
        for (int ks = 0; ks < 8; ks++) {
            const int col = ks*8 + t;
            unsigned a[4];
            a[0] = __float_as_uint(Qs[qr*APAD + col]);
            a[1] = __float_as_uint(Qs[(qr+8)*APAD + col]);
            a[2] = __float_as_uint(Qs[qr*APAD + col + 4]);
            a[3] = __float_as_uint(Qs[(qr+8)*APAD + col + 4]);
#pragma unroll
            for (int nf = 0; nf < 8; nf++) {
                unsigned bf[2];
                bf[0] = __float_as_uint(Ks[(nf*8+g)*APAD + col]);
                bf[1] = __float_as_uint(Ks[(nf*8+g)*APAD + col + 4]);
                mma8(sc[nf], a, bf);
            }
        }

#pragma unroll
        for (int nf = 0; nf < 8; nf++) {
#pragma unroll
            for (int ci = 0; ci < 2; ci++) {
                int jj = nf*8 + 2*t + ci;
                int j = jv[jj];
                int jmv = jmt[jj], jdv = jdt[jj];
                bool ok0 = (j <= r0) && ((jdv == id0) || (jmv >= STRIDE - SUMC));
                bool ok1 = (j <= r1) && ((jdv == id1) || (jmv >= STRIDE - SUMC));
                sc[nf][ci]     = ok0 ? sc[nf][ci]     * 0.125f : -1e30f;
                sc[nf][2 + ci] = ok1 ? sc[nf][2 + ci] * 0.125f : -1e30f;
            }
        }

        float mx0 = -1e30f, mx1 = -1e30f;
#pragma unroll
        for (int nf = 0; nf < 8; nf++) {
            mx0 = fmaxf(mx0, fmaxf(sc[nf][0], sc[nf][1]));
            mx1 = fmaxf(mx1, fmaxf(sc[nf][2], sc[nf][3]));
        }
        mx0 = fmaxf(mx0, __shfl_xor_sync(0xffffffffu, mx0, 1));
        mx0 = fmaxf(mx0, __shfl_xor_sync(0xffffffffu, mx0, 2));
        mx1 = fmaxf(mx1, __shfl_xor_sync(0xffffffffu, mx1, 1));
        mx1 = fmaxf(mx1, __shfl_xor_sync(0xffffffffu, mx1, 2));
        float nm0 = fmaxf(m0r, mx0), nm1 = fmaxf(m1r, mx1);
        float al0 = __expf(m0r - nm0), al1 = __expf(m1r - nm1);
        float ps0 = 0.f, ps1 = 0.f;
#pragma unroll
        for (int nf = 0; nf < 8; nf++) {
            float p0 = __expf(sc[nf][0] - nm0); sc[nf][0] = p0; ps0 += p0;
            float p1 = __expf(sc[nf][1] - nm0); sc[nf][1] = p1; ps0 += p1;
            float p2 = __expf(sc[nf][2] - nm1); sc[nf][2] = p2; ps1 += p2;
            float p3 = __expf(sc[nf][3] - nm1); sc[nf][3] = p3; ps1 += p3;
        }
        ps0 += __shfl_xor_sync(0xffffffffu, ps0, 1);
        ps0 += __shfl_xor_sync(0xffffffffu, ps0, 2);
        ps1 += __shfl_xor_sync(0xffffffffu, ps1, 1);
        ps1 += __shfl_xor_sync(0xffffffffu, ps1, 2);
        m0r = nm0; m1r = nm1;
        l0 = l0*al0 + ps0;
        l1 = l1*al1 + ps1;
#pragma unroll
        for (int nf = 0; nf < 8; nf++) {
            o[nf][0] *= al0; o[nf][1] *= al0;
            o[nf][2] *= al1; o[nf][3] *= al1;
        }

#pragma unroll
        for (int nf = 0; nf < 8; nf++) {
            Ps[qr*APAD     + nf*8 + 2*t]     = rtf(sc[nf][0]);
            Ps[qr*APAD     + nf*8 + 2*t + 1] = rtf(sc[nf][1]);
            Ps[(qr+8)*APAD + nf*8 + 2*t]     = rtf(sc[nf][2]);
            Ps[(qr+8)*APAD + nf*8 + 2*t + 1] = rtf(sc[nf][3]);
        }
        __syncwarp();

#pragma unroll
        for (int ks = 0; ks < 8; ks++) {
            const int col = ks*8 + t;
            unsigned a[4];
            a[0] = __float_as_uint(Ps[qr*APAD + col]);
            a[1] = __float_as_uint(Ps[(qr+8)*APAD + col]);
            a[2] = __float_as_uint(Ps[qr*APAD + col + 4]);
            a[3] = __float_as_uint(Ps[(qr+8)*APAD + col + 4]);
#pragma unroll
            for (int nf = 0; nf < 8; nf++) {
                unsigned bf[2];
                bf[0] = __float_as_uint(Vs[col*APAD     + nf*8 + g]);
                bf[1] = __float_as_uint(Vs[(col+4)*APAD + nf*8 + g]);
                mma8(o[nf], a, bf);
            }
        }
        __syncwarp();
    }

    const float inv0 = 1.f / l0, inv1 = 1.f / l1;
#pragma unroll
    for (int nf = 0; nf < 8; nf++) {
        int d = h*HD + nf*8 + 2*t;
        *(float2*)&g_o[((size_t)b*SS + r0)*HH + d] =
            make_float2(rtf(o[nf][0]*inv0), rtf(o[nf][1]*inv0));
        *(float2*)&g_o[((size_t)b*SS + r1)*HH + d] =
            make_float2(rtf(o[nf][2]*inv1), rtf(o[nf][3]*inv1));
    }
}

// ---------------------------------------------------------------------------
// Output projection, tf32 mma, pre-rounded operands.
// ---------------------------------------------------------------------------
__global__ __launch_bounds__(256, 2)
void oproj_mma(float* __restrict__ out)
{
    extern __shared__ float sm[];
    float* Abuf[2] = { sm,            sm + 128*RP   };
    float* Bbuf[2] = { sm + 2*128*RP, sm + 3*128*RP };

    const int n0 = blockIdx.x * 128;
    const int m0 = blockIdx.y * 128;

    const int tid  = threadIdx.x;
    const int warp = tid >> 5;
    const int lane = tid & 31;
    const int g = lane >> 2;
    const int t = lane & 3;
    const int wm = warp >> 2;
    const int wn = warp & 3;

    float c[4][4][4];
#pragma unroll
    for (int i = 0; i < 4; i++)
#pragma unroll
        for (int j = 0; j < 4; j++)
#pragma unroll
            for (int k = 0; k < 4; k++) c[i][j][k] = 0.f;

#pragma unroll
    for (int i = 0; i < 4; i++) {
        int f = tid + i*256;
        int r = f >> 3, c4 = (f & 7) * 4;
        cpa16(Abuf[0] + r*RP + c4, g_o  + (size_t)(m0+r)*HH + c4);
        cpa16(Bbuf[0] + r*RP + c4, g_wot + (size_t)(n0+r)*HH + c4);
    }
    asm volatile("cp.async.commit_group;");

    const int NT = HH / 32;
    for (int ti = 0; ti < NT; ti++) {
        asm volatile("cp.async.wait_group 0;");
        __syncthreads();
        const int cur = ti & 1;
        if (ti + 1 < NT) {
            const int k0 = (ti+1) * 32;
            const int nxt = cur ^ 1;
#pragma unroll
            for (int i = 0; i < 4; i++) {
                int f = tid + i*256;
                int r = f >> 3, c4 = (f & 7) * 4;
                cpa16(Abuf[nxt] + r*RP + c4, g_o  + (size_t)(m0+r)*HH + k0 + c4);
                cpa16(Bbuf[nxt] + r*RP + c4, g_wot + (size_t)(n0+r)*HH + k0 + c4);
            }
            asm volatile("cp.async.commit_group;");
        }
        const float* As = Abuf[cur];
        const float* Bs = Bbuf[cur];
#pragma unroll
        for (int ks = 0; ks < 4; ks++) {
            const int col = ks*8 + t;
            unsigned a[4][4], b[4][2];
#pragma unroll
            for (int mf = 0; mf < 4; mf++) {
                int r = wm*64 + mf*16 + g;
                a[mf][0] = __float_as_uint(As[r*RP + col]);
                a[mf][1] = __float_as_uint(As[(r+8)*RP + col]);
                a[mf][2] = __float_as_uint(As[r*RP + col + 4]);
                a[mf][3] = __float_as_uint(As[(r+8)*RP + col + 4]);
            }
#pragma unroll
            for (int nf = 0; nf < 4; nf++) {
                int n = wn*32 + nf*8 + g;
                b[nf][0] = __float_as_uint(Bs[n*RP + col]);
                b[nf][1] = __float_as_uint(Bs[n*RP + col + 4]);
            }
#pragma unroll
            for (int mf = 0; mf < 4; mf++)
#pragma unroll
                for (int nf = 0; nf < 4; nf++)
                    mma8(c[mf][nf], a[mf], b[nf]);
        }
        __syncthreads();
    }

#pragma unroll
    for (int mf = 0; mf < 4; mf++) {
#pragma unroll
        for (int half = 0; half < 2; half++) {
            int m = m0 + wm*64 + mf*16 + g + half*8;
#pragma unroll
            for (int nf = 0; nf < 4; nf++) {
                int n = n0 + wn*32 + nf*8 + 2*t;
                float2 v2 = half ? make_float2(c[mf][nf][2], c[mf][nf][3])
                                 : make_float2(c[mf][nf][0], c[mf][nf][1]);
                *(float2*)&out[(size_t)m*HH + n] = v2;
            }
        }
    }
}

// ---------------------------------------------------------------------------
extern "C" void kernel_launch(void* const* d_in, const int* in_sizes, int n_in,
                              void* d_out, int out_size)
{
    const float* x  = (const float*)d_in[0];
    const float* Wq = (const float*)d_in[1];
    const float* Wk = (const float*)d_in[2];
    const float* Wv = (const float*)d_in[3];
    const float* Wo = (const float*)d_in[4];
    float* out = (float*)d_out;

    cudaFuncSetAttribute(qkv_mma,    cudaFuncAttributeMaxDynamicSharedMemorySize, GEMM_SMEM);
    cudaFuncSetAttribute(attn_win,   cudaFuncAttributeMaxDynamicSharedMemorySize, ATTN_SMEM_W);
    cudaFuncSetAttribute(attn_res,   cudaFuncAttributeMaxDynamicSharedMemorySize, ATTN_SMEM_W);
    cudaFuncSetAttribute(attn_fixed, cudaFuncAttributeMaxDynamicSharedMemorySize, ATTN_SMEM_F);
    cudaFuncSetAttribute(oproj_mma,  cudaFuncAttributeMaxDynamicSharedMemorySize, GEMM_SMEM);

    precvt<<<(XF4 + 4*WF4 + 255)/256, 256>>>(x, Wq, Wk, Wv, Wo);
    qkv_mma<<<dim3(24, 32), 256, GEMM_SMEM>>>();
    attn_win  <<<dim3(SS/64, 8, BB), 128, ATTN_SMEM_W>>>();
    attn_res  <<<dim3(STRIDE, 8, BB), 128, ATTN_SMEM_W>>>();
    attn_fixed<<<dim3(SS/64, 8, BB), 128, ATTN_SMEM_F>>>();
    attn_merge<<<2048, 256>>>();
    oproj_mma<<<dim3(8, 32), 256, GEMM_SMEM>>>(out);
}

// round 8
// speedup vs baseline: 4.6658x; 1.0387x over previous
#include <cuda_runtime.h>
#include <math.h>

// Problem constants
#define BB 2
#define SS 2048
#define HH 1024
#define NH 16
#define HD 64
#define MM (BB*SS)
#define STRIDE 45
#define SUMC 1

// Scratch (device globals: allocation-free per harness rules)
__device__ float g_q[BB*NH*SS*HD];   // [B, nh, S, hd]  (tf32-rounded)
__device__ float g_k[BB*NH*SS*HD];
__device__ float g_v[BB*NH*SS*HD];
__device__ float g_o[BB*SS*HH];      // attention out, [B, S, H] (tf32-rounded)
__device__ float g_xt[MM*HH];        // tf32-rounded inputs/weights
__device__ float g_wt[3*HH*HH];      // Wq, Wk, Wv
__device__ float g_wot[HH*HH];
// strided-head split-softmax partials
__device__ float g_oA[BB*8*SS*HD];
__device__ float g_oB[BB*8*SS*HD];
__device__ float g_mA[BB*8*SS];
__device__ float g_lA[BB*8*SS];
__device__ float g_mB[BB*8*SS];
__device__ float g_lB[BB*8*SS];

// ---------------------------------------------------------------------------
// helpers
// ---------------------------------------------------------------------------
__device__ __forceinline__ unsigned f2tf(float x) {
    unsigned u; asm("cvt.rna.tf32.f32 %0, %1;" : "=r"(u) : "f"(x)); return u;
}
__device__ __forceinline__ float rtf(float x) { return __uint_as_float(f2tf(x)); }
__device__ __forceinline__ void mma8(float c[4], const unsigned a[4], const unsigned b[2]) {
    asm volatile("mma.sync.aligned.m16n8k8.row.col.f32.tf32.tf32.f32 "
        "{%0,%1,%2,%3}, {%4,%5,%6,%7}, {%8,%9}, {%0,%1,%2,%3};"
        : "+f"(c[0]), "+f"(c[1]), "+f"(c[2]), "+f"(c[3])
        : "r"(a[0]), "r"(a[1]), "r"(a[2]), "r"(a[3]), "r"(b[0]), "r"(b[1]));
}
__device__ __forceinline__ void cpa16(float* s, const float* g) {
    unsigned sa = (unsigned)__cvta_generic_to_shared(s);
    asm volatile("cp.async.cg.shared.global [%0], [%1], 16;" :: "r"(sa), "l"(g));
}

// ---------------------------------------------------------------------------
// Prologue: round x / Wq / Wk / Wv / Wo to tf32 (stored as f32 bits).
// ---------------------------------------------------------------------------
#define XF4 (MM*HH/4)      // 1048576
#define WF4 (HH*HH/4)      // 262144

__global__ __launch_bounds__(256)
void precvt(const float* __restrict__ x,  const float* __restrict__ Wq,
            const float* __restrict__ Wk, const float* __restrict__ Wv,
            const float* __restrict__ Wo)
{
    int i = blockIdx.x * 256 + threadIdx.x;
    const float4* s; float4* d; int k;
    if (i < XF4) { s = (const float4*)x; d = (float4*)g_xt; k = i; }
    else {
        int w = (i - XF4) >> 18;           // / WF4
        k = (i - XF4) & (WF4 - 1);
        const float* srcs[4] = { Wq, Wk, Wv, Wo };
        s = (const float4*)srcs[w];
        d = (w < 3) ? (float4*)(g_wt + (size_t)w*HH*HH) : (float4*)g_wot;
    }
    float4 v = s[k];
    v.x = rtf(v.x); v.y = rtf(v.y); v.z = rtf(v.z); v.w = rtf(v.w);
    d[k] = v;
}

// ---------------------------------------------------------------------------
// GEMM v2: 128x256 block tile, 8 warps, 64x64 warp tiles, K-tile 32,
// double-buffered cp.async. MMA:LDS = 1:1 per k-step.
// ---------------------------------------------------------------------------
#define RP 36
#define GEMM_SMEM2 (2*(128+256)*RP*4)   // 110592 B

// shared mainloop body: computes C(128x256) = A(m0..m0+127, :) * B(n0..n0+255, :)^T
// A rows from matA (row-major [*,HH]), B rows from matB (row-major [HH,HH]).
template<int DO_RTF>
__device__ __forceinline__ void gemm_body(const float* __restrict__ matA,
                                          const float* __restrict__ matB,
                                          int m0, int n0,
                                          float c[4][8][4], float* sm)
{
    float* Abuf[2] = { sm,                        sm + (128+256)*RP };
    float* Bbuf[2] = { sm + 128*RP,               sm + (128+256)*RP + 128*RP };

    const int tid  = threadIdx.x;
#pragma unroll
    for (int i = 0; i < 12; i++) {
        int f = tid + i*256;                 // 0..3071
        if (f < 1024) {
            int r = f >> 3, c4 = (f & 7) * 4;
            cpa16(Abuf[0] + r*RP + c4, matA + (size_t)(m0+r)*HH + c4);
        } else {
            int fb = f - 1024;
            int r = fb >> 3, c4 = (fb & 7) * 4;
            cpa16(Bbuf[0] + r*RP + c4, matB + (size_t)(n0+r)*HH + c4);
        }
    }
    asm volatile("cp.async.commit_group;");

    const int warp = tid >> 5;
    const int lane = tid & 31;
    const int g = lane >> 2;
    const int t = lane & 3;
    const int wm = warp >> 2;     // 0..1
    const int wn = warp & 3;      // 0..3

    const int NT = HH / 32;
    for (int ti = 0; ti < NT; ti++) {
        asm volatile("cp.async.wait_group 0;");
        __syncthreads();
        const int cur = ti & 1;
        if (ti + 1 < NT) {
            const int k0 = (ti+1) * 32;
            const int nxt = cur ^ 1;
#pragma unroll
            for (int i = 0; i < 12; i++) {
                int f = tid + i*256;
                if (f < 1024) {
                    int r = f >> 3, c4 = (f & 7) * 4;
                    cpa16(Abuf[nxt] + r*RP + c4, matA + (size_t)(m0+r)*HH + k0 + c4);
                } else {
                    int fb = f - 1024;
                    int r = fb >> 3, c4 = (fb & 7) * 4;
                    cpa16(Bbuf[nxt] + r*RP + c4, matB + (size_t)(n0+r)*HH + k0 + c4);
                }
            }
            asm volatile("cp.async.commit_group;");
        }
        const float* As = Abuf[cur];
        const float* Bs = Bbuf[cur];
#pragma unroll
        for (int ks = 0; ks < 4; ks++) {
            const int col = ks*8 + t;
            unsigned a[4][4], b[8][2];
#pragma unroll
            for (int mf = 0; mf < 4; mf++) {
                int r = wm*64 + mf*16 + g;
                a[mf][0] = __float_as_uint(As[r*RP + col]);
                a[mf][1] = __float_as_uint(As[(r+8)*RP + col]);
                a[mf][2] = __float_as_uint(As[r*RP + col + 4]);
                a[mf][3] = __float_as_uint(As[(r+8)*RP + col + 4]);
            }
#pragma unroll
            for (int nf = 0; nf < 8; nf++) {
                int n = wn*64 + nf*8 + g;
                b[nf][0] = __float_as_uint(Bs[n*RP + col]);
                b[nf][1] = __float_as_uint(Bs[n*RP + col + 4]);
            }
#pragma unroll
            for (int mf = 0; mf < 4; mf++)
#pragma unroll
                for (int nf = 0; nf < 8; nf++)
                    mma8(c[mf][nf], a[mf], b[nf]);
        }
        __syncthreads();
    }
}

__global__ __launch_bounds__(256, 1)
void qkv_mma()
{
    extern __shared__ float sm[];
    const int sel = blockIdx.x >> 2;               // 0..2
    const int n0 = (blockIdx.x & 3) * 256;
    const int m0 = blockIdx.y * 128;
    const float* __restrict__ W = g_wt + (size_t)sel*HH*HH;

    float c[4][8][4];
#pragma unroll
    for (int i = 0; i < 4; i++)
#pragma unroll
        for (int j = 0; j < 8; j++)
#pragma unroll
            for (int k = 0; k < 4; k++) c[i][j][k] = 0.f;

    gemm_body<1>(g_xt, W, m0, n0, c, sm);

    const int tid  = threadIdx.x;
    const int warp = tid >> 5;
    const int lane = tid & 31;
    const int g = lane >> 2;
    const int t = lane & 3;
    const int wm = warp >> 2;
    const int wn = warp & 3;

    float* dst = (sel == 0) ? g_q : (sel == 1) ? g_k : g_v;
#pragma unroll
    for (int mf = 0; mf < 4; mf++) {
#pragma unroll
        for (int half = 0; half < 2; half++) {
            int m = m0 + wm*64 + mf*16 + g + half*8;
            int bb = m >> 11, s = m & 2047;
#pragma unroll
            for (int nf = 0; nf < 8; nf++) {
                int n = n0 + wn*64 + nf*8 + 2*t;
                int h = n >> 6, d = n & 63;
                float2 v2 = half ? make_float2(c[mf][nf][2], c[mf][nf][3])
                                 : make_float2(c[mf][nf][0], c[mf][nf][1]);
                v2.x = rtf(v2.x); v2.y = rtf(v2.y);
                *(float2*)&dst[(((size_t)(bb*NH + h))*SS + s)*HD + d] = v2;
            }
        }
    }
}

__global__ __launch_bounds__(256, 1)
void oproj_mma(float* __restrict__ out)
{
    extern __shared__ float sm[];
    const int n0 = blockIdx.x * 256;
    const int m0 = blockIdx.y * 128;

    float c[4][8][4];
#pragma unroll
    for (int i = 0; i < 4; i++)
#pragma unroll
        for (int j = 0; j < 8; j++)
#pragma unroll
            for (int k = 0; k < 4; k++) c[i][j][k] = 0.f;

    gemm_body<0>(g_o, g_wot, m0, n0, c, sm);

    const int tid  = threadIdx.x;
    const int warp = tid >> 5;
    const int lane = tid & 31;
    const int g = lane >> 2;
    const int t = lane & 3;
    const int wm = warp >> 2;
    const int wn = warp & 3;

#pragma unroll
    for (int mf = 0; mf < 4; mf++) {
#pragma unroll
        for (int half = 0; half < 2; half++) {
            int m = m0 + wm*64 + mf*16 + g + half*8;
#pragma unroll
            for (int nf = 0; nf < 8; nf++) {
                int n = n0 + wn*64 + nf*8 + 2*t;
                float2 v2 = half ? make_float2(c[mf][nf][2], c[mf][nf][3])
                                 : make_float2(c[mf][nf][0], c[mf][nf][1]);
                *(float2*)&out[(size_t)m*HH + n] = v2;
            }
        }
    }
}

// ---------------------------------------------------------------------------
// Strided heads, part A: window columns [max(0,i0-44), i0+64) (<=108 cols,
// <=2 K-tiles) with the FULL strided mask. Writes unnormalized partials.
// ---------------------------------------------------------------------------
#define APAD 68
#define ATTN_SMEM_W ((4*64*APAD + 128) * 4)

__global__ __launch_bounds__(128)
void attn_win()
{
    extern __shared__ float sm[];
    float* Qs = sm;
    float* Ks = sm + 64*APAD;
    float* Vs = sm + 2*64*APAD;
    float* Ps = sm + 3*64*APAD;
    int* jv = (int*)(sm + 4*64*APAD);
    int* jm = jv + 64;

    const int qt = blockIdx.x, h = blockIdx.y, b = blockIdx.z;
    const int i0 = qt * 64;
    const int lo = (i0 >= 44) ? i0 - 44 : 0;
    const int ncols = i0 + 64 - lo;
    const int NT = (ncols + 63) >> 6;

    const float* __restrict__ qb = g_q + (size_t)(b*NH + h) * SS * HD;
    const float* __restrict__ kb = g_k + (size_t)(b*NH + h) * SS * HD;
    const float* __restrict__ vb = g_v + (size_t)(b*NH + h) * SS * HD;

    const int tid = threadIdx.x;
    const int warp = tid >> 5, lane = tid & 31;
    const int g = lane >> 2, t = lane & 3;

#pragma unroll
    for (int i = 0; i < 8; i++) {
        int f = tid + i*128;
        int r = f >> 4, c4 = (f & 15) * 4;
        *(float4*)(Qs + r*APAD + c4) = *(const float4*)(qb + (size_t)(i0+r)*HD + c4);
    }

    const int r0 = i0 + warp*16 + g;
    const int r1 = r0 + 8;
    const int im0 = r0 % STRIDE, im1 = r1 % STRIDE;

    float o[8][4];
#pragma unroll
    for (int i = 0; i < 8; i++)
#pragma unroll
        for (int k = 0; k < 4; k++) o[i][k] = 0.f;
    float m0r = -1e30f, m1r = -1e30f, l0 = 0.f, l1 = 0.f;

    for (int ti = 0; ti < NT; ti++) {
        __syncthreads();
        if (tid < 64) {
            int p = ti*64 + tid;
            int j = (p < ncols) ? (lo + p) : (1 << 28);
            jv[tid] = j;
            jm[tid] = (lo + p) % STRIDE;
        }
#pragma unroll
        for (int i = 0; i < 8; i++) {
            int f = tid + i*128;
            int r = f >> 4, c4 = (f & 15) * 4;
            int p = ti*64 + r;
            int j = (p < ncols) ? (lo + p) : lo;
            *(float4*)(Ks + r*APAD + c4) = *(const float4*)(kb + (size_t)j*HD + c4);
            *(float4*)(Vs + r*APAD + c4) = *(const float4*)(vb + (size_t)j*HD + c4);
        }
        __syncthreads();

        float sc[8][4];
#pragma unroll
        for (int i = 0; i < 8; i++)
#pragma unroll
            for (int k = 0; k < 4; k++) sc[i][k] = 0.f;
        const int qr = warp*16 + g;
#pragma unroll
        for (int ks = 0; ks < 8; ks++) {
            const int col = ks*8 + t;
            unsigned a[4];
            a[0] = __float_as_uint(Qs[qr*APAD + col]);
            a[1] = __float_as_uint(Qs[(qr+8)*APAD + col]);
            a[2] = __float_as_uint(Qs[qr*APAD + col + 4]);
            a[3] = __float_as_uint(Qs[(qr+8)*APAD + col + 4]);
#pragma unroll
            for (int nf = 0; nf < 8; nf++) {
                unsigned bf[2];
                bf[0] = __float_as_uint(Ks[(nf*8+g)*APAD + col]);
                bf[1] = __float_as_uint(Ks[(nf*8+g)*APAD + col + 4]);
                mma8(sc[nf], a, bf);
            }
        }

#pragma unroll
        for (int nf = 0; nf < 8; nf++) {
#pragma unroll
            for (int ci = 0; ci < 2; ci++) {
                int jj = nf*8 + 2*t + ci;
                int j = jv[jj];
                int jmv = jm[jj];
                bool ok0 = (j <= r0) && ((r0 - j < STRIDE) || (jmv == im0));
                bool ok1 = (j <= r1) && ((r1 - j < STRIDE) || (jmv == im1));
                sc[nf][ci]     = ok0 ? sc[nf][ci]     * 0.125f : -1e30f;
                sc[nf][2 + ci] = ok1 ? sc[nf][2 + ci] * 0.125f : -1e30f;
            }
        }

        float mx0 = -1e30f, mx1 = -1e30f;
#pragma unroll
        for (int nf = 0; nf < 8; nf++) {
            mx0 = fmaxf(mx0, fmaxf(sc[nf][0], sc[nf][1]));
            mx1 = fmaxf(mx1, fmaxf(sc[nf][2], sc[nf][3]));
        }
        mx0 = fmaxf(mx0, __shfl_xor_sync(0xffffffffu, mx0, 1));
        mx0 = fmaxf(mx0, __shfl_xor_sync(0xffffffffu, mx0, 2));
        mx1 = fmaxf(mx1, __shfl_xor_sync(0xffffffffu, mx1, 1));
        mx1 = fmaxf(mx1, __shfl_xor_sync(0xffffffffu, mx1, 2));
        float nm0 = fmaxf(m0r, mx0), nm1 = fmaxf(m1r, mx1);
        float al0 = __expf(m0r - nm0), al1 = __expf(m1r - nm1);
        float ps0 = 0.f, ps1 = 0.f;
#pragma unroll
        for (int nf = 0; nf < 8; nf++) {
            float p0 = __expf(sc[nf][0] - nm0); sc[nf][0] = p0; ps0 += p0;
            float p1 = __expf(sc[nf][1] - nm0); sc[nf][1] = p1; ps0 += p1;
            float p2 = __expf(sc[nf][2] - nm1); sc[nf][2] = p2; ps1 += p2;
            float p3 = __expf(sc[nf][3] - nm1); sc[nf][3] = p3; ps1 += p3;
        }
        ps0 += __shfl_xor_sync(0xffffffffu, ps0, 1);
        ps0 += __shfl_xor_sync(0xffffffffu, ps0, 2);
        ps1 += __shfl_xor_sync(0xffffffffu, ps1, 1);
        ps1 += __shfl_xor_sync(0xffffffffu, ps1, 2);
        m0r = nm0; m1r = nm1;
        l0 = l0*al0 + ps0;
        l1 = l1*al1 + ps1;
#pragma unroll
        for (int nf = 0; nf < 8; nf++) {
            o[nf][0] *= al0; o[nf][1] *= al0;
            o[nf][2] *= al1; o[nf][3] *= al1;
        }

#pragma unroll
        for (int nf = 0; nf < 8; nf++) {
            Ps[qr*APAD     + nf*8 + 2*t]     = rtf(sc[nf][0]);
            Ps[qr*APAD     + nf*8 + 2*t + 1] = rtf(sc[nf][1]);
            Ps[(qr+8)*APAD + nf*8 + 2*t]     = rtf(sc[nf][2]);
            Ps[(qr+8)*APAD + nf*8 + 2*t + 1] = rtf(sc[nf][3]);
        }
        __syncwarp();

#pragma unroll
        for (int ks = 0; ks < 8; ks++) {
            const int col = ks*8 + t;
            unsigned a[4];
            a[0] = __float_as_uint(Ps[qr*APAD + col]);
            a[1] = __float_as_uint(Ps[(qr+8)*APAD + col]);
            a[2] = __float_as_uint(Ps[qr*APAD + col + 4]);
            a[3] = __float_as_uint(Ps[(qr+8)*APAD + col + 4]);
#pragma unroll
            for (int nf = 0; nf < 8; nf++) {
                unsigned bf[2];
                bf[0] = __float_as_uint(Vs[col*APAD     + nf*8 + g]);
                bf[1] = __float_as_uint(Vs[(col+4)*APAD + nf*8 + g]);
                mma8(o[nf], a, bf);
            }
        }
        __syncwarp();
    }

    const size_t rowbase = ((size_t)(b*8 + h)) * SS;
#pragma unroll
    for (int nf = 0; nf < 8; nf++) {
        int d = nf*8 + 2*t;
        *(float2*)&g_oA[(rowbase + r0)*HD + d] = make_float2(o[nf][0], o[nf][1]);
        *(float2*)&g_oA[(rowbase + r1)*HD + d] = make_float2(o[nf][2], o[nf][3]);
    }
    if (t == 0) {
        g_mA[rowbase + r0] = m0r; g_lA[rowbase + r0] = l0;
        g_mA[rowbase + r1] = m1r; g_lA[rowbase + r1] = l1;
    }
}

// ---------------------------------------------------------------------------
// Strided heads, part B: residue-grouped columns (unchanged from R7).
// ---------------------------------------------------------------------------
__global__ __launch_bounds__(128)
void attn_res()
{
    extern __shared__ float sm[];
    float* Qs = sm;
    float* Ks = sm + 64*APAD;
    float* Vs = sm + 2*64*APAD;
    float* Ps = sm + 3*64*APAD;

    const int r  = blockIdx.x;
    const int h  = blockIdx.y;
    const int b  = blockIdx.z;

    const float* __restrict__ qb = g_q + (size_t)(b*NH + h) * SS * HD;
    const float* __restrict__ kb = g_k + (size_t)(b*NH + h) * SS * HD;
    const float* __restrict__ vb = g_v + (size_t)(b*NH + h) * SS * HD;

    const int tid = threadIdx.x;
    const int warp = tid >> 5, lane = tid & 31;
    const int g = lane >> 2, t = lane & 3;

#pragma unroll
    for (int i = 0; i < 8; i++) {
        int f = tid + i*128;
        int p = f >> 4, c4 = (f & 15) * 4;
        int iq = r + STRIDE*p; if (iq >= SS) iq = 0;
        *(float4*)(Qs + p*APAD + c4) = *(const float4*)(qb + (size_t)iq*HD + c4);
        *(float4*)(Ks + p*APAD + c4) = *(const float4*)(kb + (size_t)iq*HD + c4);
        *(float4*)(Vs + p*APAD + c4) = *(const float4*)(vb + (size_t)iq*HD + c4);
    }
    __syncthreads();

    const int p0 = warp*16 + g;
    const int p1 = p0 + 8;
    const int i0r = r + STRIDE*p0;
    const int i1r = r + STRIDE*p1;
    const int lo0 = (i0r < SS) ? max(0, ((i0r >> 6) << 6) - 44) : 0;
    const int lo1 = (i1r < SS) ? max(0, ((i1r >> 6) << 6) - 44) : 0;

    float sc[8][4];
#pragma unroll
    for (int i = 0; i < 8; i++)
#pragma unroll
        for (int k = 0; k < 4; k++) sc[i][k] = 0.f;
#pragma unroll
    for (int ks = 0; ks < 8; ks++) {
        const int col = ks*8 + t;
        unsigned a[4];
        a[0] = __float_as_uint(Qs[p0*APAD + col]);
        a[1] = __float_as_uint(Qs[p1*APAD + col]);
        a[2] = __float_as_uint(Qs[p0*APAD + col + 4]);
        a[3] = __float_as_uint(Qs[p1*APAD + col + 4]);
#pragma unroll
        for (int nf = 0; nf < 8; nf++) {
            unsigned bf[2];
            bf[0] = __float_as_uint(Ks[(nf*8+g)*APAD + col]);
            bf[1] = __float_as_uint(Ks[(nf*8+g)*APAD + col + 4]);
            mma8(sc[nf], a, bf);
        }
    }

#pragma unroll
    for (int nf = 0; nf < 8; nf++) {
#pragma unroll
        for (int ci = 0; ci < 2; ci++) {
            int jj = nf*8 + 2*t + ci;
            int j = r + STRIDE*jj;
            sc[nf][ci]     = (j < lo0) ? sc[nf][ci]     * 0.125f : -1e30f;
            sc[nf][2 + ci] = (j < lo1) ? sc[nf][2 + ci] * 0.125f : -1e30f;
        }
    }

    float mx0 = -1e30f, mx1 = -1e30f;
#pragma unroll
    for (int nf = 0; nf < 8; nf++) {
        mx0 = fmaxf(mx0, fmaxf(sc[nf][0], sc[nf][1]));
        mx1 = fmaxf(mx1, fmaxf(sc[nf][2], sc[nf][3]));
    }
    mx0 = fmaxf(mx0, __shfl_xor_sync(0xffffffffu, mx0, 1));
    mx0 = fmaxf(mx0, __shfl_xor_sync(0xffffffffu, mx0, 2));
    mx1 = fmaxf(mx1, __shfl_xor_sync(0xffffffffu, mx1, 1));
    mx1 = fmaxf(mx1, __shfl_xor_sync(0xffffffffu, mx1, 2));
    float ps0 = 0.f, ps1 = 0.f;
#pragma unroll
    for (int nf = 0; nf < 8; nf++) {
        float p0v = (sc[nf][0] > -5e29f) ? __expf(sc[nf][0] - mx0) : 0.f; sc[nf][0] = p0v; ps0 += p0v;
        float p1v = (sc[nf][1] > -5e29f) ? __expf(sc[nf][1] - mx0) : 0.f; sc[nf][1] = p1v; ps0 += p1v;
        float p2v = (sc[nf][2] > -5e29f) ? __expf(sc[nf][2] - mx1) : 0.f; sc[nf][2] = p2v; ps1 += p2v;
        float p3v = (sc[nf][3] > -5e29f) ? __expf(sc[nf][3] - mx1) : 0.f; sc[nf][3] = p3v; ps1 += p3v;
    }
    ps0 += __shfl_xor_sync(0xffffffffu, ps0, 1);
    ps0 += __shfl_xor_sync(0xffffffffu, ps0, 2);
    ps1 += __shfl_xor_sync(0xffffffffu, ps1, 1);
    ps1 += __shfl_xor_sync(0xffffffffu, ps1, 2);

#pragma unroll
    for (int nf = 0; nf < 8; nf++) {
        Ps[p0*APAD + nf*8 + 2*t]     = rtf(sc[nf][0]);
        Ps[p0*APAD + nf*8 + 2*t + 1] = rtf(sc[nf][1]);
        Ps[p1*APAD + nf*8 + 2*t]     = rtf(sc[nf][2]);
        Ps[p1*APAD + nf*8 + 2*t + 1] = rtf(sc[nf][3]);
    }
    __syncwarp();

    float o[8][4];
#pragma unroll
    for (int i = 0; i < 8; i++)
#pragma unroll
        for (int k = 0; k < 4; k++) o[i][k] = 0.f;
#pragma unroll
    for (int ks = 0; ks < 8; ks++) {
        const int col = ks*8 + t;
        unsigned a[4];
        a[0] = __float_as_uint(Ps[p0*APAD + col]);
        a[1] = __float_as_uint(Ps[p1*APAD + col]);
        a[2] = __float_as_uint(Ps[p0*APAD + col + 4]);
        a[3] = __float_as_uint(Ps[p1*APAD + col + 4]);
#pragma unroll
        for (int nf = 0; nf < 8; nf++) {
            unsigned bf[2];
            bf[0] = __float_as_uint(Vs[col*APAD     + nf*8 + g]);
            bf[1] = __float_as_uint(Vs[(col+4)*APAD + nf*8 + g]);
            mma8(o[nf], a, bf);
        }
    }
    __syncwarp();

    const size_t rowbase = ((size_t)(b*8 + h)) * SS;
    if (i0r < SS) {
#pragma unroll
        for (int nf = 0; nf < 8; nf++) {
            int d = nf*8 + 2*t;
            *(float2*)&g_oB[(rowbase + i0r)*HD + d] = make_float2(o[nf][0], o[nf][1]);
        }
        if (t == 0) { g_mB[rowbase + i0r] = mx0; g_lB[rowbase + i0r] = ps0; }
    }
    if (i1r < SS) {
#pragma unroll
        for (int nf = 0; nf < 8; nf++) {
            int d = nf*8 + 2*t;
            *(float2*)&g_oB[(rowbase + i1r)*HD + d] = make_float2(o[nf][2], o[nf][3]);
        }
        if (t == 0) { g_mB[rowbase + i1r] = mx1; g_lB[rowbase + i1r] = ps1; }
    }
}

// ---------------------------------------------------------------------------
// Merge A + B partials for strided heads -> g_o (tf32-rounded).
// ---------------------------------------------------------------------------
__global__ __launch_bounds__(256)
void attn_merge()
{
    int idx = blockIdx.x * 256 + threadIdx.x;
    int d4 = idx & 15;
    int i  = (idx >> 4) & 2047;
    int h  = (idx >> 15) & 7;
    int b  = idx >> 18;
    size_t row = ((size_t)(b*8 + h)) * SS + i;

    float mA = g_mA[row], lA = g_lA[row];
    float mB = g_mB[row], lB = g_lB[row];
    float m = fmaxf(mA, mB);
    float eA = __expf(mA - m), eB = __expf(mB - m);
    float L = lA*eA + lB*eB;
    float inv = 1.f / L;

    float4 a = *(const float4*)&g_oA[row*HD + d4*4];
    float4 c = *(const float4*)&g_oB[row*HD + d4*4];
    float4 o;
    o.x = rtf((a.x*eA + c.x*eB) * inv);
    o.y = rtf((a.y*eA + c.y*eB) * inv);
    o.z = rtf((a.z*eA + c.z*eB) * inv);
    o.w = rtf((a.w*eA + c.w*eB) * inv);
    *(float4*)&g_o[((size_t)b*SS + i)*HH + h*HD + d4*4] = o;
}

// ---------------------------------------------------------------------------
// Fixed-head flash attention (heads 8..15) with column gathering (unchanged).
// ---------------------------------------------------------------------------
#define ATTN_SMEM_F ((4*64*APAD + 192) * 4)

__global__ __launch_bounds__(128)
void attn_fixed()
{
    extern __shared__ float sm[];
    float* Qs = sm;
    float* Ks = sm + 64*APAD;
    float* Vs = sm + 2*64*APAD;
    float* Ps = sm + 3*64*APAD;
    int* jv = (int*)(sm + 4*64*APAD);
    int* jmt = jv + 64;
    int* jdt = jmt + 64;

    const int qt = blockIdx.x;
    const int h  = 8 + blockIdx.y;
    const int b  = blockIdx.z;
    const int i0 = qt * 64;

    const int nsum   = i0 / STRIDE;
    const int bstart = nsum * STRIDE;
    const int ncols  = nsum + (i0 + 64 - bstart);
    const int NT     = (ncols + 63) >> 6;

    const float* __restrict__ qb = g_q + (size_t)(b*NH + h) * SS * HD;
    const float* __restrict__ kb = g_k + (size_t)(b*NH + h) * SS * HD;
    const float* __restrict__ vb = g_v + (size_t)(b*NH + h) * SS * HD;

    const int tid = threadIdx.x;
    const int warp = tid >> 5, lane = tid & 31;
    const int g = lane >> 2, t = lane & 3;

#pragma unroll
    for (int i = 0; i < 8; i++) {
        int f = tid + i*128;
        int r = f >> 4, c4 = (f & 15) * 4;
        *(float4*)(Qs + r*APAD + c4) = *(const float4*)(qb + (size_t)(i0+r)*HD + c4);
    }

    const int r0 = i0 + warp*16 + g;
    const int r1 = r0 + 8;
    const int id0 = r0 / STRIDE, id1 = r1 / STRIDE;

    float o[8][4];
#pragma unroll
    for (int i = 0; i < 8; i++)
#pragma unroll
        for (int k = 0; k < 4; k++) o[i][k] = 0.f;
    float m0r = -1e30f, m1r = -1e30f, l0 = 0.f, l1 = 0.f;

    for (int ti = 0; ti < NT; ti++) {
        __syncthreads();
        if (tid < 64) {
            int p = ti*64 + tid;
            int j = (p < ncols) ? ((p < nsum) ? (STRIDE*p + STRIDE-1)
                                              : (bstart + p - nsum))
                                : (1 << 28);
            jv[tid] = j;
            jmt[tid] = j % STRIDE;
            jdt[tid] = j / STRIDE;
        }
#pragma unroll
        for (int i = 0; i < 8; i++) {
            int f = tid + i*128;
            int r = f >> 4, c4 = (f & 15) * 4;
            int p = ti*64 + r;
            int j = (p < ncols) ? ((p < nsum) ? (STRIDE*p + STRIDE-1)
                                              : (bstart + p - nsum)) : 0;
            *(float4*)(Ks + r*APAD + c4) = *(const float4*)(kb + (size_t)j*HD + c4);
            *(float4*)(Vs + r*APAD + c4) = *(const float4*)(vb + (size_t)j*HD + c4);
        }
        __syncthreads();

        float sc[8][4];
#pragma unroll
        for (int i = 0; i < 8; i++)
#pragma unroll
            for (int k = 0; k < 4; k++) sc[i][k] = 0.f;
        const int qr = warp*16 + g;
#pragma unroll
        for (int ks = 0; ks < 8; ks++) {
            const int col = ks*8 + t;
            unsigned a[4];
            a[0] = __float_as_uint(Qs[qr*APAD + col]);
            a[1] = __float_as_uint(Qs[(qr+8)*APAD + col]);
            a[2] = __float_as_uint(Qs[qr*APAD + col + 4]);
            a[3] = __float_as_uint(Qs[(qr+8)*APAD + col + 4]);
#pragma unroll
            for (int nf = 0; nf < 8; nf++) {
                unsigned bf[2];
                bf[0] = __float_as_uint(Ks[(nf*8+g)*APAD + col]);
                bf[1] = __float_as_uint(Ks[(nf*8+g)*APAD + col + 4]);
                mma8(sc[nf], a, bf);
            }
        }

#pragma unroll
        for (int nf = 0; nf < 8; nf++) {
#pragma unroll
            for (int ci = 0; ci < 2; ci++) {
                int jj = nf*8 + 2*t + ci;
                int j = jv[jj];
                int jmv = jmt[jj], jdv = jdt[jj];
                bool ok0 = (j <= r0) && ((jdv == id0) || (jmv >= STRIDE - SUMC));
                bool ok1 = (j <= r1) && ((jdv == id1) || (jmv >= STRIDE - SUMC));
                sc[nf][ci]     = ok0 ? sc[nf][ci]     * 0.125f : -1e30f;
                sc[nf][2 + ci] = ok1 ? sc[nf][2 + ci] * 0.125f : -1e30f;
            }
        }

        float mx0 = -1e30f, mx1 = -1e30f;
#pragma unroll
        for (int nf = 0; nf < 8; nf++) {
            mx0 = fmaxf(mx0, fmaxf(sc[nf][0], sc[nf][1]));
            mx1 = fmaxf(mx1, fmaxf(sc[nf][2], sc[nf][3]));
        }
        mx0 = fmaxf(mx0, __shfl_xor_sync(0xffffffffu, mx0, 1));
        mx0 = fmaxf(mx0, __shfl_xor_sync(0xffffffffu, mx0, 2));
        mx1 = fmaxf(mx1, __shfl_xor_sync(0xffffffffu, mx1, 1));
        mx1 = fmaxf(mx1, __shfl_xor_sync(0xffffffffu, mx1, 2));
        float nm0 = fmaxf(m0r, mx0), nm1 = fmaxf(m1r, mx1);
        float al0 = __expf(m0r - nm0), al1 = __expf(m1r - nm1);
        float ps0 = 0.f, ps1 = 0.f;
#pragma unroll
        for (int nf = 0; nf < 8; nf++) {
            float p0 = __expf(sc[nf][0] - nm0); sc[nf][0] = p0; ps0 += p0;
            float p1 = __expf(sc[nf][1] - nm0); sc[nf][1] = p1; ps0 += p1;
            float p2 = __expf(sc[nf][2] - nm1); sc[nf][2] = p2; ps1 += p2;
            float p3 = __expf(sc[nf][3] - nm1); sc[nf][3] = p3; ps1 += p3;
        }
        ps0 += __shfl_xor_sync(0xffffffffu, ps0, 1);
        ps0 += __shfl_xor_sync(0xffffffffu, ps0, 2);
        ps1 += __shfl_xor_sync(0xffffffffu, ps1, 1);
        ps1 += __shfl_xor_sync(0xffffffffu, ps1, 2);
        m0r = nm0; m1r = nm1;
        l0 = l0*al0 + ps0;
        l1 = l1*al1 + ps1;
#pragma unroll
        for (int nf = 0; nf < 8; nf++) {
            o[nf][0] *= al0; o[nf][1] *= al0;
            o[nf][2] *= al1; o[nf][3] *= al1;
        }

#pragma unroll
        for (int nf = 0; nf < 8; nf++) {
            Ps[qr*APAD     + nf*8 + 2*t]     = rtf(sc[nf][0]);
            Ps[qr*APAD     + nf*8 + 2*t + 1] = rtf(sc[nf][1]);
            Ps[(qr+8)*APAD + nf*8 + 2*t]     = rtf(sc[nf][2]);
            Ps[(qr+8)*APAD + nf*8 + 2*t + 1] = rtf(sc[nf][3]);
        }
        __syncwarp();

#pragma unroll
        for (int ks = 0; ks < 8; ks++) {
            const int col = ks*8 + t;
            unsigned a[4];
            a[0] = __float_as_uint(Ps[qr*APAD + col]);
            a[1] = __float_as_uint(Ps[(qr+8)*APAD + col]);
            a[2] = __float_as_uint(Ps[qr*APAD + col + 4]);
            a[3] = __float_as_uint(Ps[(qr+8)*APAD + col + 4]);
#pragma unroll
            for (int nf = 0; nf < 8; nf++) {
                unsigned bf[2];
                bf[0] = __float_as_uint(Vs[col*APAD     + nf*8 + g]);
                bf[1] = __float_as_uint(Vs[(col+4)*APAD + nf*8 + g]);
                mma8(o[nf], a, bf);
            }
        }
        __syncwarp();
    }

    const float inv0 = 1.f / l0, inv1 = 1.f / l1;
#pragma unroll
    for (int nf = 0; nf < 8; nf++) {
        int d = h*HD + nf*8 + 2*t;
        *(float2*)&g_o[((size_t)b*SS + r0)*HH + d] =
            make_float2(rtf(o[nf][0]*inv0), rtf(o[nf][1]*inv0));
        *(float2*)&g_o[((size_t)b*SS + r1)*HH + d] =
            make_float2(rtf(o[nf][2]*inv1), rtf(o[nf][3]*inv1));
    }
}

// ---------------------------------------------------------------------------
extern "C" void kernel_launch(void* const* d_in, const int* in_sizes, int n_in,
                              void* d_out, int out_size)
{
    const float* x  = (const float*)d_in[0];
    const float* Wq = (const float*)d_in[1];
    const float* Wk = (const float*)d_in[2];
    const float* Wv = (const float*)d_in[3];
    const float* Wo = (const float*)d_in[4];
    float* out = (float*)d_out;

    cudaFuncSetAttribute(qkv_mma,    cudaFuncAttributeMaxDynamicSharedMemorySize, GEMM_SMEM2);
    cudaFuncSetAttribute(attn_win,   cudaFuncAttributeMaxDynamicSharedMemorySize, ATTN_SMEM_W);
    cudaFuncSetAttribute(attn_res,   cudaFuncAttributeMaxDynamicSharedMemorySize, ATTN_SMEM_W);
    cudaFuncSetAttribute(attn_fixed, cudaFuncAttributeMaxDynamicSharedMemorySize, ATTN_SMEM_F);
    cudaFuncSetAttribute(oproj_mma,  cudaFuncAttributeMaxDynamicSharedMemorySize, GEMM_SMEM2);

    precvt<<<(XF4 + 4*WF4 + 255)/256, 256>>>(x, Wq, Wk, Wv, Wo);
    qkv_mma<<<dim3(12, 32), 256, GEMM_SMEM2>>>();
    attn_win  <<<dim3(SS/64, 8, BB), 128, ATTN_SMEM_W>>>();
    attn_res  <<<dim3(STRIDE, 8, BB), 128, ATTN_SMEM_W>>>();
    attn_fixed<<<dim3(SS/64, 8, BB), 128, ATTN_SMEM_F>>>();
    attn_merge<<<2048, 256>>>();
    oproj_mma<<<dim3(4, 32), 256, GEMM_SMEM2>>>(out);
}

// round 10
// speedup vs baseline: 4.8862x; 1.0472x over previous
#include <cuda_runtime.h>
#include <math.h>
#include <stdint.h>

// Problem constants
#define BB 2
#define SS 2048
#define HH 1024
#define NH 16
#define HD 64
#define MM (BB*SS)
#define STRIDE 45
#define SUMC 1

// Scratch (device globals: allocation-free per harness rules)
__device__ float g_q[BB*NH*SS*HD];   // [B, nh, S, hd]  (tf32-rounded)
__device__ float g_k[BB*NH*SS*HD];
__device__ float g_v[BB*NH*SS*HD];
__device__ float g_o[BB*SS*HH];      // attention out, [B, S, H] (tf32-rounded)
__device__ float g_xt[MM*HH];        // tf32-rounded inputs/weights
__device__ float g_wt[3*HH*HH];      // Wq, Wk, Wv
__device__ float g_wot[HH*HH];
// strided-head split-softmax partials
__device__ float g_oA[BB*8*SS*HD];
__device__ float g_oB[BB*8*SS*HD];
__device__ float g_mA[BB*8*SS];
__device__ float g_lA[BB*8*SS];
__device__ float g_mB[BB*8*SS];
__device__ float g_lB[BB*8*SS];

// ---------------------------------------------------------------------------
// helpers
// ---------------------------------------------------------------------------
__device__ __forceinline__ unsigned f2tf(float x) {
    unsigned u; asm("cvt.rna.tf32.f32 %0, %1;" : "=r"(u) : "f"(x)); return u;
}
__device__ __forceinline__ float rtf(float x) { return __uint_as_float(f2tf(x)); }
__device__ __forceinline__ void mma8(float c[4], const unsigned a[4], const unsigned b[2]) {
    asm volatile("mma.sync.aligned.m16n8k8.row.col.f32.tf32.tf32.f32 "
        "{%0,%1,%2,%3}, {%4,%5,%6,%7}, {%8,%9}, {%0,%1,%2,%3};"
        : "+f"(c[0]), "+f"(c[1]), "+f"(c[2]), "+f"(c[3])
        : "r"(a[0]), "r"(a[1]), "r"(a[2]), "r"(a[3]), "r"(b[0]), "r"(b[1]));
}
__device__ __forceinline__ void cpa16(float* s, const float* g) {
    unsigned sa = (unsigned)__cvta_generic_to_shared(s);
    asm volatile("cp.async.cg.shared.global [%0], [%1], 16;" :: "r"(sa), "l"(g));
}

// ---------------------------------------------------------------------------
// Prologue: round x / Wq / Wk / Wv / Wo to tf32 (stored as f32 bits).
// ---------------------------------------------------------------------------
#define XF4 (MM*HH/4)      // 1048576
#define WF4 (HH*HH/4)      // 262144

__global__ __launch_bounds__(256)
void precvt(const float* __restrict__ x,  const float* __restrict__ Wq,
            const float* __restrict__ Wk, const float* __restrict__ Wv,
            const float* __restrict__ Wo)
{
    int i = blockIdx.x * 256 + threadIdx.x;
    const float4* s; float4* d; int k;
    if (i < XF4) { s = (const float4*)x; d = (float4*)g_xt; k = i; }
    else {
        int w = (i - XF4) >> 18;
        k = (i - XF4) & (WF4 - 1);
        const float* srcs[4] = { Wq, Wk, Wv, Wo };
        s = (const float4*)srcs[w];
        d = (w < 3) ? (float4*)(g_wt + (size_t)w*HH*HH) : (float4*)g_wot;
    }
    float4 v = s[k];
    v.x = rtf(v.x); v.y = rtf(v.y); v.z = rtf(v.z); v.w = rtf(v.w);
    d[k] = v;
}

// ---------------------------------------------------------------------------
// GEMM: 128x256 block tile, 8 warps, 64x64 warp tiles, K-tile 32,
// double-buffered cp.async. (R8 version — best passing.)
// ---------------------------------------------------------------------------
#define RP 36
#define GEMM_SMEM2 (2*(128+256)*RP*4)   // 110592 B

template<int DO_RTF>
__device__ __forceinline__ void gemm_body(const float* __restrict__ matA,
                                          const float* __restrict__ matB,
                                          int m0, int n0,
                                          float c[4][8][4], float* sm)
{
    float* Abuf[2] = { sm,          sm + (128+256)*RP };
    float* Bbuf[2] = { sm + 128*RP, sm + (128+256)*RP + 128*RP };

    const int tid  = threadIdx.x;
#pragma unroll
    for (int i = 0; i < 12; i++) {
        int f = tid + i*256;
        if (f < 1024) {
            int r = f >> 3, c4 = (f & 7) * 4;
            cpa16(Abuf[0] + r*RP + c4, matA + (size_t)(m0+r)*HH + c4);
        } else {
            int fb = f - 1024;
            int r = fb >> 3, c4 = (fb & 7) * 4;
            cpa16(Bbuf[0] + r*RP + c4, matB + (size_t)(n0+r)*HH + c4);
        }
    }
    asm volatile("cp.async.commit_group;");

    const int warp = tid >> 5;
    const int lane = tid & 31;
    const int g = lane >> 2;
    const int t = lane & 3;
    const int wm = warp >> 2;
    const int wn = warp & 3;

    const int NT = HH / 32;
    for (int ti = 0; ti < NT; ti++) {
        asm volatile("cp.async.wait_group 0;");
        __syncthreads();
        const int cur = ti & 1;
        if (ti + 1 < NT) {
            const int k0 = (ti+1) * 32;
            const int nxt = cur ^ 1;
#pragma unroll
            for (int i = 0; i < 12; i++) {
                int f = tid + i*256;
                if (f < 1024) {
                    int r = f >> 3, c4 = (f & 7) * 4;
                    cpa16(Abuf[nxt] + r*RP + c4, matA + (size_t)(m0+r)*HH + k0 + c4);
                } else {
                    int fb = f - 1024;
                    int r = fb >> 3, c4 = (fb & 7) * 4;
                    cpa16(Bbuf[nxt] + r*RP + c4, matB + (size_t)(n0+r)*HH + k0 + c4);
                }
            }
            asm volatile("cp.async.commit_group;");
        }
        const float* As = Abuf[cur];
        const float* Bs = Bbuf[cur];
#pragma unroll
        for (int ks = 0; ks < 4; ks++) {
            const int col = ks*8 + t;
            unsigned a[4][4], b[8][2];
#pragma unroll
            for (int mf = 0; mf < 4; mf++) {
                int r = wm*64 + mf*16 + g;
                a[mf][0] = __float_as_uint(As[r*RP + col]);
                a[mf][1] = __float_as_uint(As[(r+8)*RP + col]);
                a[mf][2] = __float_as_uint(As[r*RP + col + 4]);
                a[mf][3] = __float_as_uint(As[(r+8)*RP + col + 4]);
            }
#pragma unroll
            for (int nf = 0; nf < 8; nf++) {
                int n = wn*64 + nf*8 + g;
                b[nf][0] = __float_as_uint(Bs[n*RP + col]);
                b[nf][1] = __float_as_uint(Bs[n*RP + col + 4]);
            }
#pragma unroll
            for (int mf = 0; mf < 4; mf++)
#pragma unroll
                for (int nf = 0; nf < 8; nf++)
                    mma8(c[mf][nf], a[mf], b[nf]);
        }
        __syncthreads();
    }
}

__global__ __launch_bounds__(256, 1)
void qkv_mma()
{
    extern __shared__ float sm[];
    const int sel = blockIdx.x >> 2;
    const int n0 = (blockIdx.x & 3) * 256;
    const int m0 = blockIdx.y * 128;
    const float* __restrict__ W = g_wt + (size_t)sel*HH*HH;

    float c[4][8][4];
#pragma unroll
    for (int i = 0; i < 4; i++)
#pragma unroll
        for (int j = 0; j < 8; j++)
#pragma unroll
            for (int k = 0; k < 4; k++) c[i][j][k] = 0.f;

    gemm_body<1>(g_xt, W, m0, n0, c, sm);

    const int tid  = threadIdx.x;
    const int warp = tid >> 5;
    const int lane = tid & 31;
    const int g = lane >> 2;
    const int t = lane & 3;
    const int wm = warp >> 2;
    const int wn = warp & 3;

    float* dst = (sel == 0) ? g_q : (sel == 1) ? g_k : g_v;
#pragma unroll
    for (int mf = 0; mf < 4; mf++) {
#pragma unroll
        for (int half = 0; half < 2; half++) {
            int m = m0 + wm*64 + mf*16 + g + half*8;
            int bb = m >> 11, s = m & 2047;
#pragma unroll
            for (int nf = 0; nf < 8; nf++) {
                int n = n0 + wn*64 + nf*8 + 2*t;
                int h = n >> 6, d = n & 63;
                float2 v2 = half ? make_float2(c[mf][nf][2], c[mf][nf][3])
                                 : make_float2(c[mf][nf][0], c[mf][nf][1]);
                v2.x = rtf(v2.x); v2.y = rtf(v2.y);
                *(float2*)&dst[(((size_t)(bb*NH + h))*SS + s)*HD + d] = v2;
            }
        }
    }
}

__global__ __launch_bounds__(256, 1)
void oproj_mma(float* __restrict__ out)
{
    extern __shared__ float sm[];
    const int n0 = blockIdx.x * 256;
    const int m0 = blockIdx.y * 128;

    float c[4][8][4];
#pragma unroll
    for (int i = 0; i < 4; i++)
#pragma unroll
        for (int j = 0; j < 8; j++)
#pragma unroll
            for (int k = 0; k < 4; k++) c[i][j][k] = 0.f;

    gemm_body<0>(g_o, g_wot, m0, n0, c, sm);

    const int tid  = threadIdx.x;
    const int warp = tid >> 5;
    const int lane = tid & 31;
    const int g = lane >> 2;
    const int t = lane & 3;
    const int wm = warp >> 2;
    const int wn = warp & 3;

#pragma unroll
    for (int mf = 0; mf < 4; mf++) {
#pragma unroll
        for (int half = 0; half < 2; half++) {
            int m = m0 + wm*64 + mf*16 + g + half*8;
#pragma unroll
            for (int nf = 0; nf < 8; nf++) {
                int n = n0 + wn*64 + nf*8 + 2*t;
                float2 v2 = half ? make_float2(c[mf][nf][2], c[mf][nf][3])
                                 : make_float2(c[mf][nf][0], c[mf][nf][1]);
                *(float2*)&out[(size_t)m*HH + n] = v2;
            }
        }
    }
}

// ---------------------------------------------------------------------------
// Fused attention kernel: one launch covers fixed-head blocks, window blocks
// and residue blocks, dispatched on blockIdx.x. 128 threads, 70400 B smem.
// Longest-running bodies (fixed, <=3 tiles) are scheduled first.
// ---------------------------------------------------------------------------
#define APAD 68
#define ATTN_SMEM_A ((4*64*APAD + 192) * 4)   // 70400 B
#define NBLK_FIXED 512                        // 32 qt * 8 h * 2 b
#define NBLK_WIN   512
#define NBLK_RES   720                        // 45 r * 8 h * 2 b

// ---- window part (strided heads, part A) ----
__device__ __forceinline__ void win_body(int v, float* sm)
{
    float* Qs = sm;
    float* Ks = sm + 64*APAD;
    float* Vs = sm + 2*64*APAD;
    float* Ps = sm + 3*64*APAD;
    int* jv = (int*)(sm + 4*64*APAD);
    int* jm = jv + 64;

    const int qt = v & 31, h = (v >> 5) & 7, b = v >> 8;
    const int i0 = qt * 64;
    const int lo = (i0 >= 44) ? i0 - 44 : 0;
    const int ncols = i0 + 64 - lo;
    const int NT = (ncols + 63) >> 6;

    const float* __restrict__ qb = g_q + (size_t)(b*NH + h) * SS * HD;
    const float* __restrict__ kb = g_k + (size_t)(b*NH + h) * SS * HD;
    const float* __restrict__ vb = g_v + (size_t)(b*NH + h) * SS * HD;

    const int tid = threadIdx.x;
    const int warp = tid >> 5, lane = tid & 31;
    const int g = lane >> 2, t = lane & 3;

#pragma unroll
    for (int i = 0; i < 8; i++) {
        int f = tid + i*128;
        int r = f >> 4, c4 = (f & 15) * 4;
        *(float4*)(Qs + r*APAD + c4) = *(const float4*)(qb + (size_t)(i0+r)*HD + c4);
    }

    const int r0 = i0 + warp*16 + g;
    const int r1 = r0 + 8;
    const int im0 = r0 % STRIDE, im1 = r1 % STRIDE;

    float o[8][4];
#pragma unroll
    for (int i = 0; i < 8; i++)
#pragma unroll
        for (int k = 0; k < 4; k++) o[i][k] = 0.f;
    float m0r = -1e30f, m1r = -1e30f, l0 = 0.f, l1 = 0.f;

    for (int ti = 0; ti < NT; ti++) {
        __syncthreads();
        if (tid < 64) {
            int p = ti*64 + tid;
            int j = (p < ncols) ? (lo + p) : (1 << 28);
            jv[tid] = j;
            jm[tid] = (lo + p) % STRIDE;
        }
#pragma unroll
        for (int i = 0; i < 8; i++) {
            int f = tid + i*128;
            int r = f >> 4, c4 = (f & 15) * 4;
            int p = ti*64 + r;
            int j = (p < ncols) ? (lo + p) : lo;
            *(float4*)(Ks + r*APAD + c4) = *(const float4*)(kb + (size_t)j*HD + c4);
            *(float4*)(Vs + r*APAD + c4) = *(const float4*)(vb + (size_t)j*HD + c4);
        }
        __syncthreads();

        float sc[8][4];
#pragma unroll
        for (int i = 0; i < 8; i++)
#pragma unroll
            for (int k = 0; k < 4; k++) sc[i][k] = 0.f;
        const int qr = warp*16 + g;
#pragma unroll
        for (int ks = 0; ks < 8; ks++) {
            const int col = ks*8 + t;
            unsigned a[4];
            a[0] = __float_as_uint(Qs[qr*APAD + col]);
            a[1] = __float_as_uint(Qs[(qr+8)*APAD + col]);
            a[2] = __float_as_uint(Qs[qr*APAD + col + 4]);
            a[3] = __float_as_uint(Qs[(qr+8)*APAD + col + 4]);
#pragma unroll
            for (int nf = 0; nf < 8; nf++) {
                unsigned bf[2];
                bf[0] = __float_as_uint(Ks[(nf*8+g)*APAD + col]);
                bf[1] = __float_as_uint(Ks[(nf*8+g)*APAD + col + 4]);
                mma8(sc[nf], a, bf);
            }
        }

#pragma unroll
        for (int nf = 0; nf < 8; nf++) {
#pragma unroll
            for (int ci = 0; ci < 2; ci++) {
                int jj = nf*8 + 2*t + ci;
                int j = jv[jj];
                int jmv = jm[jj];
                bool ok0 = (j <= r0) && ((r0 - j < STRIDE) || (jmv == im0));
                bool ok1 = (j <= r1) && ((r1 - j < STRIDE) || (jmv == im1));
                sc[nf][ci]     = ok0 ? sc[nf][ci]     * 0.125f : -1e30f;
                sc[nf][2 + ci] = ok1 ? sc[nf][2 + ci] * 0.125f : -1e30f;
            }
        }

        float mx0 = -1e30f, mx1 = -1e30f;
#pragma unroll
        for (int nf = 0; nf < 8; nf++) {
            mx0 = fmaxf(mx0, fmaxf(sc[nf][0], sc[nf][1]));
            mx1 = fmaxf(mx1, fmaxf(sc[nf][2], sc[nf][3]));
        }
        mx0 = fmaxf(mx0, __shfl_xor_sync(0xffffffffu, mx0, 1));
        mx0 = fmaxf(mx0, __shfl_xor_sync(0xffffffffu, mx0, 2));
        mx1 = fmaxf(mx1, __shfl_xor_sync(0xffffffffu, mx1, 1));
        mx1 = fmaxf(mx1, __shfl_xor_sync(0xffffffffu, mx1, 2));
        float nm0 = fmaxf(m0r, mx0), nm1 = fmaxf(m1r, mx1);
        float al0 = __expf(m0r - nm0), al1 = __expf(m1r - nm1);
        float ps0 = 0.f, ps1 = 0.f;
#pragma unroll
        for (int nf = 0; nf < 8; nf++) {
            float p0 = __expf(sc[nf][0] - nm0); sc[nf][0] = p0; ps0 += p0;
            float p1 = __expf(sc[nf][1] - nm0); sc[nf][1] = p1; ps0 += p1;
            float p2 = __expf(sc[nf][2] - nm1); sc[nf][2] = p2; ps1 += p2;
            float p3 = __expf(sc[nf][3] - nm1); sc[nf][3] = p3; ps1 += p3;
        }
        ps0 += __shfl_xor_sync(0xffffffffu, ps0, 1);
        ps0 += __shfl_xor_sync(0xffffffffu, ps0, 2);
        ps1 += __shfl_xor_sync(0xffffffffu, ps1, 1);
        ps1 += __shfl_xor_sync(0xffffffffu, ps1, 2);
        m0r = nm0; m1r = nm1;
        l0 = l0*al0 + ps0;
        l1 = l1*al1 + ps1;
#pragma unroll
        for (int nf = 0; nf < 8; nf++) {
            o[nf][0] *= al0; o[nf][1] *= al0;
            o[nf][2] *= al1; o[nf][3] *= al1;
        }

#pragma unroll
        for (int nf = 0; nf < 8; nf++) {
            Ps[qr*APAD     + nf*8 + 2*t]     = rtf(sc[nf][0]);
            Ps[qr*APAD     + nf*8 + 2*t + 1] = rtf(sc[nf][1]);
            Ps[(qr+8)*APAD + nf*8 + 2*t]     = rtf(sc[nf][2]);
            Ps[(qr+8)*APAD + nf*8 + 2*t + 1] = rtf(sc[nf][3]);
        }
        __syncwarp();

#pragma unroll
        for (int ks = 0; ks < 8; ks++) {
            const int col = ks*8 + t;
            unsigned a[4];
            a[0] = __float_as_uint(Ps[qr*APAD + col]);
            a[1] = __float_as_uint(Ps[(qr+8)*APAD + col]);
            a[2] = __float_as_uint(Ps[qr*APAD + col + 4]);
            a[3] = __float_as_uint(Ps[(qr+8)*APAD + col + 4]);
#pragma unroll
            for (int nf = 0; nf < 8; nf++) {
                unsigned bf[2];
                bf[0] = __float_as_uint(Vs[col*APAD     + nf*8 + g]);
                bf[1] = __float_as_uint(Vs[(col+4)*APAD + nf*8 + g]);
                mma8(o[nf], a, bf);
            }
        }
        __syncwarp();
    }

    const size_t rowbase = ((size_t)(b*8 + h)) * SS;
#pragma unroll
    for (int nf = 0; nf < 8; nf++) {
        int d = nf*8 + 2*t;
        *(float2*)&g_oA[(rowbase + r0)*HD + d] = make_float2(o[nf][0], o[nf][1]);
        *(float2*)&g_oA[(rowbase + r1)*HD + d] = make_float2(o[nf][2], o[nf][3]);
    }
    if (t == 0) {
        g_mA[rowbase + r0] = m0r; g_lA[rowbase + r0] = l0;
        g_mA[rowbase + r1] = m1r; g_lA[rowbase + r1] = l1;
    }
}

// ---- residue part (strided heads, part B) ----
__device__ __forceinline__ void res_body(int v, float* sm)
{
    float* Qs = sm;
    float* Ks = sm + 64*APAD;
    float* Vs = sm + 2*64*APAD;
    float* Ps = sm + 3*64*APAD;

    const int r  = v % STRIDE;
    const int rest = v / STRIDE;
    const int h  = rest & 7;
    const int b  = rest >> 3;

    const float* __restrict__ qb = g_q + (size_t)(b*NH + h) * SS * HD;
    const float* __restrict__ kb = g_k + (size_t)(b*NH + h) * SS * HD;
    const float* __restrict__ vb = g_v + (size_t)(b*NH + h) * SS * HD;

    const int tid = threadIdx.x;
    const int warp = tid >> 5, lane = tid & 31;
    const int g = lane >> 2, t = lane & 3;

#pragma unroll
    for (int i = 0; i < 8; i++) {
        int f = tid + i*128;
        int p = f >> 4, c4 = (f & 15) * 4;
        int iq = r + STRIDE*p; if (iq >= SS) iq = 0;
        *(float4*)(Qs + p*APAD + c4) = *(const float4*)(qb + (size_t)iq*HD + c4);
        *(float4*)(Ks + p*APAD + c4) = *(const float4*)(kb + (size_t)iq*HD + c4);
        *(float4*)(Vs + p*APAD + c4) = *(const float4*)(vb + (size_t)iq*HD + c4);
    }
    __syncthreads();

    const int p0 = warp*16 + g;
    const int p1 = p0 + 8;
    const int i0r = r + STRIDE*p0;
    const int i1r = r + STRIDE*p1;
    const int lo0 = (i0r < SS) ? max(0, ((i0r >> 6) << 6) - 44) : 0;
    const int lo1 = (i1r < SS) ? max(0, ((i1r >> 6) << 6) - 44) : 0;

    float sc[8][4];
#pragma unroll
    for (int i = 0; i < 8; i++)
#pragma unroll
        for (int k = 0; k < 4; k++) sc[i][k] = 0.f;
#pragma unroll
    for (int ks = 0; ks < 8; ks++) {
        const int col = ks*8 + t;
        unsigned a[4];
        a[0] = __float_as_uint(Qs[p0*APAD + col]);
        a[1] = __float_as_uint(Qs[p1*APAD + col]);
        a[2] = __float_as_uint(Qs[p0*APAD + col + 4]);
        a[3] = __float_as_uint(Qs[p1*APAD + col + 4]);
#pragma unroll
        for (int nf = 0; nf < 8; nf++) {
            unsigned bf[2];
            bf[0] = __float_as_uint(Ks[(nf*8+g)*APAD + col]);
            bf[1] = __float_as_uint(Ks[(nf*8+g)*APAD + col + 4]);
            mma8(sc[nf], a, bf);
        }
    }

#pragma unroll
    for (int nf = 0; nf < 8; nf++) {
#pragma unroll
        for (int ci = 0; ci < 2; ci++) {
            int jj = nf*8 + 2*t + ci;
            int j = r + STRIDE*jj;
            sc[nf][ci]     = (j < lo0) ? sc[nf][ci]     * 0.125f : -1e30f;
            sc[nf][2 + ci] = (j < lo1) ? sc[nf][2 + ci] * 0.125f : -1e30f;
        }
    }

    float mx0 = -1e30f, mx1 = -1e30f;
#pragma unroll
    for (int nf = 0; nf < 8; nf++) {
        mx0 = fmaxf(mx0, fmaxf(sc[nf][0], sc[nf][1]));
        mx1 = fmaxf(mx1, fmaxf(sc[nf][2], sc[nf][3]));
    }
    mx0 = fmaxf(mx0, __shfl_xor_sync(0xffffffffu, mx0, 1));
    mx0 = fmaxf(mx0, __shfl_xor_sync(0xffffffffu, mx0, 2));
    mx1 = fmaxf(mx1, __shfl_xor_sync(0xffffffffu, mx1, 1));
    mx1 = fmaxf(mx1, __shfl_xor_sync(0xffffffffu, mx1, 2));
    float ps0 = 0.f, ps1 = 0.f;
#pragma unroll
    for (int nf = 0; nf < 8; nf++) {
        float p0v = (sc[nf][0] > -5e29f) ? __expf(sc[nf][0] - mx0) : 0.f; sc[nf][0] = p0v; ps0 += p0v;
        float p1v = (sc[nf][1] > -5e29f) ? __expf(sc[nf][1] - mx0) : 0.f; sc[nf][1] = p1v; ps0 += p1v;
        float p2v = (sc[nf][2] > -5e29f) ? __expf(sc[nf][2] - mx1) : 0.f; sc[nf][2] = p2v; ps1 += p2v;
        float p3v = (sc[nf][3] > -5e29f) ? __expf(sc[nf][3] - mx1) : 0.f; sc[nf][3] = p3v; ps1 += p3v;
    }
    ps0 += __shfl_xor_sync(0xffffffffu, ps0, 1);
    ps0 += __shfl_xor_sync(0xffffffffu, ps0, 2);
    ps1 += __shfl_xor_sync(0xffffffffu, ps1, 1);
    ps1 += __shfl_xor_sync(0xffffffffu, ps1, 2);

#pragma unroll
    for (int nf = 0; nf < 8; nf++) {
        Ps[p0*APAD + nf*8 + 2*t]     = rtf(sc[nf][0]);
        Ps[p0*APAD + nf*8 + 2*t + 1] = rtf(sc[nf][1]);
        Ps[p1*APAD + nf*8 + 2*t]     = rtf(sc[nf][2]);
        Ps[p1*APAD + nf*8 + 2*t + 1] = rtf(sc[nf][3]);
    }
    __syncwarp();

    float o[8][4];
#pragma unroll
    for (int i = 0; i < 8; i++)
#pragma unroll
        for (int k = 0; k < 4; k++) o[i][k] = 0.f;
#pragma unroll
    for (int ks = 0; ks < 8; ks++) {
        const int col = ks*8 + t;
        unsigned a[4];
        a[0] = __float_as_uint(Ps[p0*APAD + col]);
        a[1] = __float_as_uint(Ps[p1*APAD + col]);
        a[2] = __float_as_uint(Ps[p0*APAD + col + 4]);
        a[3] = __float_as_uint(Ps[p1*APAD + col + 4]);
#pragma unroll
        for (int nf = 0; nf < 8; nf++) {
            unsigned bf[2];
            bf[0] = __float_as_uint(Vs[col*APAD     + nf*8 + g]);
            bf[1] = __float_as_uint(Vs[(col+4)*APAD + nf*8 + g]);
            mma8(o[nf], a, bf);
        }
    }
    __syncwarp();

    const size_t rowbase = ((size_t)(b*8 + h)) * SS;
    if (i0r < SS) {
#pragma unroll
        for (int nf = 0; nf < 8; nf++) {
            int d = nf*8 + 2*t;
            *(float2*)&g_oB[(rowbase + i0r)*HD + d] = make_float2(o[nf][0], o[nf][1]);
        }
        if (t == 0) { g_mB[rowbase + i0r] = mx0; g_lB[rowbase + i0r] = ps0; }
    }
    if (i1r < SS) {
#pragma unroll
        for (int nf = 0; nf < 8; nf++) {
            int d = nf*8 + 2*t;
            *(float2*)&g_oB[(rowbase + i1r)*HD + d] = make_float2(o[nf][2], o[nf][3]);
        }
        if (t == 0) { g_mB[rowbase + i1r] = mx1; g_lB[rowbase + i1r] = ps1; }
    }
}

// ---- fixed heads (8..15) with column gathering ----
__device__ __forceinline__ void fixed_body(int v, float* sm)
{
    float* Qs = sm;
    float* Ks = sm + 64*APAD;
    float* Vs = sm + 2*64*APAD;
    float* Ps = sm + 3*64*APAD;
    int* jv = (int*)(sm + 4*64*APAD);
    int* jmt = jv + 64;
    int* jdt = jmt + 64;

    const int qt = v & 31;
    const int h  = 8 + ((v >> 5) & 7);
    const int b  = v >> 8;
    const int i0 = qt * 64;

    const int nsum   = i0 / STRIDE;
    const int bstart = nsum * STRIDE;
    const int ncols  = nsum + (i0 + 64 - bstart);
    const int NT     = (ncols + 63) >> 6;

    const float* __restrict__ qb = g_q + (size_t)(b*NH + h) * SS * HD;
    const float* __restrict__ kb = g_k + (size_t)(b*NH + h) * SS * HD;
    const float* __restrict__ vb = g_v + (size_t)(b*NH + h) * SS * HD;

    const int tid = threadIdx.x;
    const int warp = tid >> 5, lane = tid & 31;
    const int g = lane >> 2, t = lane & 3;

#pragma unroll
    for (int i = 0; i < 8; i++) {
        int f = tid + i*128;
        int r = f >> 4, c4 = (f & 15) * 4;
        *(float4*)(Qs + r*APAD + c4) = *(const float4*)(qb + (size_t)(i0+r)*HD + c4);
    }

    const int r0 = i0 + warp*16 + g;
    const int r1 = r0 + 8;
    const int id0 = r0 / STRIDE, id1 = r1 / STRIDE;

    float o[8][4];
#pragma unroll
    for (int i = 0; i < 8; i++)
#pragma unroll
        for (int k = 0; k < 4; k++) o[i][k] = 0.f;
    float m0r = -1e30f, m1r = -1e30f, l0 = 0.f, l1 = 0.f;

    for (int ti = 0; ti < NT; ti++) {
        __syncthreads();
        if (tid < 64) {
            int p = ti*64 + tid;
            int j = (p < ncols) ? ((p < nsum) ? (STRIDE*p + STRIDE-1)
                                              : (bstart + p - nsum))
                                : (1 << 28);
            jv[tid] = j;
            jmt[tid] = j % STRIDE;
            jdt[tid] = j / STRIDE;
        }
#pragma unroll
        for (int i = 0; i < 8; i++) {
            int f = tid + i*128;
            int r = f >> 4, c4 = (f & 15) * 4;
            int p = ti*64 + r;
            int j = (p < ncols) ? ((p < nsum) ? (STRIDE*p + STRIDE-1)
                                              : (bstart + p - nsum)) : 0;
            *(float4*)(Ks + r*APAD + c4) = *(const float4*)(kb + (size_t)j*HD + c4);
            *(float4*)(Vs + r*APAD + c4) = *(const float4*)(vb + (size_t)j*HD + c4);
        }
        __syncthreads();

        float sc[8][4];
#pragma unroll
        for (int i = 0; i < 8; i++)
#pragma unroll
            for (int k = 0; k < 4; k++) sc[i][k] = 0.f;
        const int qr = warp*16 + g;
#pragma unroll
        for (int ks = 0; ks < 8; ks++) {
            const int col = ks*8 + t;
            unsigned a[4];
            a[0] = __float_as_uint(Qs[qr*APAD + col]);
            a[1] = __float_as_uint(Qs[(qr+8)*APAD + col]);
            a[2] = __float_as_uint(Qs[qr*APAD + col + 4]);
            a[3] = __float_as_uint(Qs[(qr+8)*APAD + col + 4]);
#pragma unroll
            for (int nf = 0; nf < 8; nf++) {
                unsigned bf[2];
                bf[0] = __float_as_uint(Ks[(nf*8+g)*APAD + col]);
                bf[1] = __float_as_uint(Ks[(nf*8+g)*APAD + col + 4]);
                mma8(sc[nf], a, bf);
            }
        }

#pragma unroll
        for (int nf = 0; nf < 8; nf++) {
#pragma unroll
            for (int ci = 0; ci < 2; ci++) {
                int jj = nf*8 + 2*t + ci;
                int j = jv[jj];
                int jmv = jmt[jj], jdv = jdt[jj];
                bool ok0 = (j <= r0) && ((jdv == id0) || (jmv >= STRIDE - SUMC));
                bool ok1 = (j <= r1) && ((jdv == id1) || (jmv >= STRIDE - SUMC));
                sc[nf][ci]     = ok0 ? sc[nf][ci]     * 0.125f : -1e30f;
                sc[nf][2 + ci] = ok1 ? sc[nf][2 + ci] * 0.125f : -1e30f;
            }
        }

        float mx0 = -1e30f, mx1 = -1e30f;
#pragma unroll
        for (int nf = 0; nf < 8; nf++) {
            mx0 = fmaxf(mx0, fmaxf(sc[nf][0], sc[nf][1]));
            mx1 = fmaxf(mx1, fmaxf(sc[nf][2], sc[nf][3]));
        }
        mx0 = fmaxf(mx0, __shfl_xor_sync(0xffffffffu, mx0, 1));
        mx0 = fmaxf(mx0, __shfl_xor_sync(0xffffffffu, mx0, 2));
        mx1 = fmaxf(mx1, __shfl_xor_sync(0xffffffffu, mx1, 1));
        mx1 = fmaxf(mx1, __shfl_xor_sync(0xffffffffu, mx1, 2));
        float nm0 = fmaxf(m0r, mx0), nm1 = fmaxf(m1r, mx1);
        float al0 = __expf(m0r - nm0), al1 = __expf(m1r - nm1);
        float ps0 = 0.f, ps1 = 0.f;
#pragma unroll
        for (int nf = 0; nf < 8; nf++) {
            float p0 = __expf(sc[nf][0] - nm0); sc[nf][0] = p0; ps0 += p0;
            float p1 = __expf(sc[nf][1] - nm0); sc[nf][1] = p1; ps0 += p1;
            float p2 = __expf(sc[nf][2] - nm1); sc[nf][2] = p2; ps1 += p2;
            float p3 = __expf(sc[nf][3] - nm1); sc[nf][3] = p3; ps1 += p3;
        }
        ps0 += __shfl_xor_sync(0xffffffffu, ps0, 1);
        ps0 += __shfl_xor_sync(0xffffffffu, ps0, 2);
        ps1 += __shfl_xor_sync(0xffffffffu, ps1, 1);
        ps1 += __shfl_xor_sync(0xffffffffu, ps1, 2);
        m0r = nm0; m1r = nm1;
        l0 = l0*al0 + ps0;
        l1 = l1*al1 + ps1;
#pragma unroll
        for (int nf = 0; nf < 8; nf++) {
            o[nf][0] *= al0; o[nf][1] *= al0;
            o[nf][2] *= al1; o[nf][3] *= al1;
        }

#pragma unroll
        for (int nf = 0; nf < 8; nf++) {
            Ps[qr*APAD     + nf*8 + 2*t]     = rtf(sc[nf][0]);
            Ps[qr*APAD     + nf*8 + 2*t + 1] = rtf(sc[nf][1]);
            Ps[(qr+8)*APAD + nf*8 + 2*t]     = rtf(sc[nf][2]);
            Ps[(qr+8)*APAD + nf*8 + 2*t + 1] = rtf(sc[nf][3]);
        }
        __syncwarp();

#pragma unroll
        for (int ks = 0; ks < 8; ks++) {
            const int col = ks*8 + t;
            unsigned a[4];
            a[0] = __float_as_uint(Ps[qr*APAD + col]);
            a[1] = __float_as_uint(Ps[(qr+8)*APAD + col]);
            a[2] = __float_as_uint(Ps[qr*APAD + col + 4]);
            a[3] = __float_as_uint(Ps[(qr+8)*APAD + col + 4]);
#pragma unroll
            for (int nf = 0; nf < 8; nf++) {
                unsigned bf[2];
                bf[0] = __float_as_uint(Vs[col*APAD     + nf*8 + g]);
                bf[1] = __float_as_uint(Vs[(col+4)*APAD + nf*8 + g]);
                mma8(o[nf], a, bf);
            }
        }
        __syncwarp();
    }

    const float inv0 = 1.f / l0, inv1 = 1.f / l1;
#pragma unroll
    for (int nf = 0; nf < 8; nf++) {
        int d = h*HD + nf*8 + 2*t;
        *(float2*)&g_o[((size_t)b*SS + r0)*HH + d] =
            make_float2(rtf(o[nf][0]*inv0), rtf(o[nf][1]*inv0));
        *(float2*)&g_o[((size_t)b*SS + r1)*HH + d] =
            make_float2(rtf(o[nf][2]*inv1), rtf(o[nf][3]*inv1));
    }
}

__global__ __launch_bounds__(128)
void attn_all()
{
    extern __shared__ float sm[];
    int bid = blockIdx.x;
    if (bid < NBLK_FIXED)                 fixed_body(bid, sm);
    else if (bid < NBLK_FIXED + NBLK_WIN) win_body(bid - NBLK_FIXED, sm);
    else                                  res_body(bid - NBLK_FIXED - NBLK_WIN, sm);
}

// ---------------------------------------------------------------------------
// Merge A + B partials for strided heads -> g_o (tf32-rounded).
// ---------------------------------------------------------------------------
__global__ __launch_bounds__(256)
void attn_merge()
{
    int idx = blockIdx.x * 256 + threadIdx.x;
    int d4 = idx & 15;
    int i  = (idx >> 4) & 2047;
    int h  = (idx >> 15) & 7;
    int b  = idx >> 18;
    size_t row = ((size_t)(b*8 + h)) * SS + i;

    float mA = g_mA[row], lA = g_lA[row];
    float mB = g_mB[row], lB = g_lB[row];
    float m = fmaxf(mA, mB);
    float eA = __expf(mA - m), eB = __expf(mB - m);
    float L = lA*eA + lB*eB;
    float inv = 1.f / L;

    float4 a = *(const float4*)&g_oA[row*HD + d4*4];
    float4 c = *(const float4*)&g_oB[row*HD + d4*4];
    float4 o;
    o.x = rtf((a.x*eA + c.x*eB) * inv);
    o.y = rtf((a.y*eA + c.y*eB) * inv);
    o.z = rtf((a.z*eA + c.z*eB) * inv);
    o.w = rtf((a.w*eA + c.w*eB) * inv);
    *(float4*)&g_o[((size_t)b*SS + i)*HH + h*HD + d4*4] = o;
}

// ---------------------------------------------------------------------------
extern "C" void kernel_launch(void* const* d_in, const int* in_sizes, int n_in,
                              void* d_out, int out_size)
{
    const float* x  = (const float*)d_in[0];
    const float* Wq = (const float*)d_in[1];
    const float* Wk = (const float*)d_in[2];
    const float* Wv = (const float*)d_in[3];
    const float* Wo = (const float*)d_in[4];
    float* out = (float*)d_out;

    cudaFuncSetAttribute(qkv_mma,   cudaFuncAttributeMaxDynamicSharedMemorySize, GEMM_SMEM2);
    cudaFuncSetAttribute(oproj_mma, cudaFuncAttributeMaxDynamicSharedMemorySize, GEMM_SMEM2);
    cudaFuncSetAttribute(attn_all,  cudaFuncAttributeMaxDynamicSharedMemorySize, ATTN_SMEM_A);

    precvt<<<(XF4 + 4*WF4 + 255)/256, 256>>>(x, Wq, Wk, Wv, Wo);
    qkv_mma<<<dim3(12, 32), 256, GEMM_SMEM2>>>();
    attn_all<<<NBLK_FIXED + NBLK_WIN + NBLK_RES, 128, ATTN_SMEM_A>>>();
    attn_merge<<<2048, 256>>>();
    oproj_mma<<<dim3(4, 32), 256, GEMM_SMEM2>>>(out);
}